// round 13
// baseline (speedup 1.0000x reference)
#include <cuda_runtime.h>
#include <cuda_bf16.h>
#include <math.h>
#include <stdint.h>

// Problem constants
#define B_       2
#define S_       2048
#define DIM_     2048
#define H_       16
#define KV_LORA_ 512
#define NOPE_    128
#define ROPE_    64
#define VD_      128
#define QD_      192
#define BS_      (B_ * S_)    // 4096
#define NQC_     3648         // fused q (3072) + ckv (576) output width

// ---------------------------------------------------------------------------
// Scratch
// ---------------------------------------------------------------------------
__device__ float g_qckv[BS_ * NQC_];           // fused q | ckv   (4096 x 3648)
__device__ float g_norm[BS_ * KV_LORA_];
__device__ float g_kv  [BS_ * H_ * (NOPE_ + VD_)];
__device__ float g_qf  [B_ * H_ * S_ * QD_];   // tf32-rounded, pre-scaled
__device__ float g_kf  [B_ * H_ * S_ * QD_];   // tf32-rounded
__device__ float g_v   [B_ * H_ * S_ * VD_];   // tf32-rounded
__device__ float g_attn[BS_ * H_ * VD_];       // tf32-rounded

__device__ float g_xr   [BS_ * DIM_];
__device__ float g_wqkva[NQC_ * DIM_];         // fused wq rows | wkva rows
__device__ float g_wkvbr[H_ * 256 * KV_LORA_];
__device__ float g_wor  [DIM_ * H_ * VD_];

// ---------------------------------------------------------------------------
// Helpers
// ---------------------------------------------------------------------------
__device__ __forceinline__ float to_tf32(float x) {
    uint32_t u;
    asm("cvt.rna.tf32.f32 %0, %1;" : "=r"(u) : "f"(x));
    return __uint_as_float(u);
}
__device__ __forceinline__ uint32_t smem_u32(const void* p) {
    uint32_t a;
    asm("{ .reg .u64 t; cvta.to.shared.u64 t, %1; cvt.u32.u64 %0, t; }"
        : "=r"(a) : "l"(p));
    return a;
}
#define CPA16(dst, src, sz) \
    asm volatile("cp.async.cg.shared.global [%0], [%1], 16, %2;" \
                 :: "r"(dst), "l"(src), "r"(sz) : "memory")
#define MMA_TF32(d, a, b)                                                     \
    asm volatile(                                                             \
        "mma.sync.aligned.m16n8k8.row.col.f32.tf32.tf32.f32 "                 \
        "{%0,%1,%2,%3}, {%4,%5,%6,%7}, {%8,%9}, {%0,%1,%2,%3};"               \
        : "+f"((d)[0]), "+f"((d)[1]), "+f"((d)[2]), "+f"((d)[3])              \
        : "r"((a)[0]), "r"((a)[1]), "r"((a)[2]), "r"((a)[3]),                 \
          "r"((b)[0]), "r"((b)[1]))

// ---------------------------------------------------------------------------
// tf32 mma.sync GEMM: C[M,N] = A[M,K] @ B[N,K]^T
// CTA tile 128x256, BK=32, 256 threads = 8 warps, warp tile 64x64,
// 2-stage cp.async pipeline, 2 CTAs/SM (16 warps/SM -> tensor pipe stays fed
// across each CTA's sync/LDS phases).
// M mult 128, K mult 32, N guarded.
// ---------------------------------------------------------------------------
constexpr int MG_STR    = 36;
constexpr int MG_ABUF   = 128 * MG_STR;            // 4608 floats
constexpr int MG_BBUF   = 256 * MG_STR;            // 9216 floats
constexpr int MG_STAGE  = MG_ABUF + MG_BBUF;       // 13824 floats
constexpr unsigned MG_SMEM_BYTES = 2u * MG_STAGE * sizeof(float);  // 110592

__global__ __launch_bounds__(256, 2)
void mma_gemm(const float* __restrict__ A, const float* __restrict__ Bm,
              float* __restrict__ C, int N, int K) {
    extern __shared__ float sm[];
    const uint32_t sb = smem_u32(sm);

    const int t    = threadIdx.x;
    const int wid  = t >> 5;
    const int lane = t & 31;
    const int g    = lane >> 2;
    const int tig  = lane & 3;
    const int wm   = (wid & 1) * 64;
    const int wn   = (wid >> 1) * 64;        // 0..192
    const int m0   = blockIdx.y * 128;
    const int n0   = blockIdx.x * 256;
    const int NK   = K / 32;

    // load coordinates: A = 1024 float4 (4/thread), B = 2048 float4 (8/thread)
    int arow[4], ac4[4];
    const float* Asrc[4];
#pragma unroll
    for (int j = 0; j < 4; j++) {
        const int f = t + j * 256;
        arow[j] = f >> 3;
        ac4[j]  = f & 7;
        Asrc[j] = A + (size_t)(m0 + arow[j]) * K + ac4[j] * 4;
    }
    int brow[8], bc4[8], bsz[8];
    const float* Bsrc[8];
#pragma unroll
    for (int j = 0; j < 8; j++) {
        const int f = t + j * 256;
        brow[j] = f >> 3;               // 0..255
        bc4[j]  = f & 7;
        const int gr = n0 + brow[j];
        bsz[j]  = (gr < N) ? 16 : 0;
        Bsrc[j] = Bm + (size_t)((gr < N) ? gr : 0) * K + bc4[j] * 4;
    }

#define MG_LOAD(stg, kc)                                                        \
    do {                                                                        \
        const int k0_ = (kc) * 32;                                              \
        const uint32_t sA_ = sb + (uint32_t)((stg) * MG_STAGE) * 4u;            \
        const uint32_t sB_ = sA_ + (uint32_t)MG_ABUF * 4u;                      \
        _Pragma("unroll")                                                       \
        for (int j = 0; j < 4; j++)                                             \
            CPA16(sA_ + (uint32_t)(arow[j] * MG_STR + ac4[j] * 4) * 4u,         \
                  Asrc[j] + k0_, 16);                                           \
        _Pragma("unroll")                                                       \
        for (int j = 0; j < 8; j++)                                             \
            CPA16(sB_ + (uint32_t)(brow[j] * MG_STR + bc4[j] * 4) * 4u,         \
                  Bsrc[j] + k0_, bsz[j]);                                       \
    } while (0)

    float acc[4][8][4];
#pragma unroll
    for (int mi = 0; mi < 4; mi++)
#pragma unroll
        for (int ni = 0; ni < 8; ni++)
#pragma unroll
            for (int c = 0; c < 4; c++) acc[mi][ni][c] = 0.0f;

    MG_LOAD(0, 0);
    asm volatile("cp.async.commit_group;" ::: "memory");
    MG_LOAD(1, 1);
    asm volatile("cp.async.commit_group;" ::: "memory");

    for (int i = 0; i < NK; ++i) {
        const int cur = i & 1;
        asm volatile("cp.async.wait_group 1;" ::: "memory");
        __syncthreads();

        const float* Ab = sm + cur * MG_STAGE;
        const float* Bb = Ab + MG_ABUF;
#pragma unroll
        for (int ks = 0; ks < 4; ks++) {
            const int k0 = ks * 8;
            uint32_t a[4][4], b[8][2];
#pragma unroll
            for (int mi = 0; mi < 4; mi++) {
                const float* ap = Ab + (wm + mi * 16 + g) * MG_STR + k0 + tig;
                a[mi][0] = __float_as_uint(ap[0]);
                a[mi][1] = __float_as_uint(ap[8 * MG_STR]);
                a[mi][2] = __float_as_uint(ap[4]);
                a[mi][3] = __float_as_uint(ap[8 * MG_STR + 4]);
            }
#pragma unroll
            for (int ni = 0; ni < 8; ni++) {
                const float* bp = Bb + (wn + ni * 8 + g) * MG_STR + k0 + tig;
                b[ni][0] = __float_as_uint(bp[0]);
                b[ni][1] = __float_as_uint(bp[4]);
            }
#pragma unroll
            for (int mi = 0; mi < 4; mi++)
#pragma unroll
                for (int ni = 0; ni < 8; ni++)
                    MMA_TF32(acc[mi][ni], a[mi], b[ni]);
        }
        __syncthreads();   // all warps done reading stage `cur` before reload
        if (i + 2 < NK) MG_LOAD(cur, i + 2);
        asm volatile("cp.async.commit_group;" ::: "memory");
    }
#undef MG_LOAD

#pragma unroll
    for (int mi = 0; mi < 4; mi++) {
        const int rr = m0 + wm + mi * 16 + g;
#pragma unroll
        for (int ni = 0; ni < 8; ni++) {
            const int cc = n0 + wn + ni * 8 + tig * 2;
            if (cc < N) {
                float2 v0 = make_float2(acc[mi][ni][0], acc[mi][ni][1]);
                float2 v1 = make_float2(acc[mi][ni][2], acc[mi][ni][3]);
                *(float2*)&C[(size_t)rr * N + cc]       = v0;
                *(float2*)&C[(size_t)(rr + 8) * N + cc] = v1;
            }
        }
    }
}

// ---------------------------------------------------------------------------
// tf32 rounding pass
// ---------------------------------------------------------------------------
__global__ __launch_bounds__(256) void round_tf32_kernel(const float4* __restrict__ src,
                                                         float4* __restrict__ dst, int n4) {
    for (int i = blockIdx.x * 256 + threadIdx.x; i < n4; i += gridDim.x * 256) {
        float4 v = src[i];
        v.x = to_tf32(v.x); v.y = to_tf32(v.y);
        v.z = to_tf32(v.z); v.w = to_tf32(v.w);
        dst[i] = v;
    }
}

// ---------------------------------------------------------------------------
// RMSNorm over qckv[row, 3072:3584]; tf32-rounded out
// ---------------------------------------------------------------------------
__global__ __launch_bounds__(128) void rmsnorm_kernel(const float* __restrict__ qckv,
                                                      const float* __restrict__ w,
                                                      float* __restrict__ outp) {
    const int row = blockIdx.x;
    const int t   = threadIdx.x;
    const float* xr = qckv + (size_t)row * NQC_ + H_ * QD_;
    float v[4];
    float s = 0.f;
#pragma unroll
    for (int i = 0; i < 4; i++) { v[i] = xr[t + i * 128]; s += v[i] * v[i]; }
#pragma unroll
    for (int m = 16; m >= 1; m >>= 1) s += __shfl_xor_sync(0xffffffffu, s, m);
    __shared__ float ws[4];
    if ((t & 31) == 0) ws[t >> 5] = s;
    __syncthreads();
    s = ws[0] + ws[1] + ws[2] + ws[3];
    const float inv = rsqrtf(s * (1.0f / (float)KV_LORA_) + 1e-6f);
    float* orow = outp + (size_t)row * KV_LORA_;
#pragma unroll
    for (int i = 0; i < 4; i++) orow[t + i * 128] = to_tf32(v[i] * inv * w[t + i * 128]);
}

// ---------------------------------------------------------------------------
// RoPE + assembly from fused qckv; outputs tf32-rounded
// ---------------------------------------------------------------------------
__global__ __launch_bounds__(256) void assemble_kernel(const float* __restrict__ qckv,
                                                       const float* __restrict__ kv,
                                                       const float* __restrict__ rope,
                                                       float* __restrict__ qf,
                                                       float* __restrict__ kf,
                                                       float* __restrict__ v) {
    const int row = blockIdx.x;
    const int s   = row & (S_ - 1);
    const int b   = row >> 11;
    const int t   = threadIdx.x;

    __shared__ float cs[64], sn[64], kr[64];
    if (t < 64) {
        cs[t] = rope[(size_t)s * 128 + t];
        sn[t] = rope[(size_t)s * 128 + 64 + t];
    }
    __syncthreads();
    if (t < 64) {
        const float* cr = qckv + (size_t)row * NQC_ + H_ * QD_ + KV_LORA_;
        float k0  = cr[t];
        float rot = (t < 32) ? -cr[t + 32] : cr[t - 32];
        kr[t] = k0 * cs[t] + rot * sn[t];
    }
    __syncthreads();

    const float scale = rsqrtf((float)QD_);
    for (int idx = t; idx < H_ * QD_; idx += 256) {
        const int h = idx / QD_;
        const int d = idx - h * QD_;
        const size_t dst = ((size_t)(b * H_ + h) * S_ + s) * QD_ + d;
        const float* qrow = qckv + (size_t)row * NQC_ + h * QD_;
        float qv;
        if (d < NOPE_) {
            qv = qrow[d];
        } else {
            const int r   = d - NOPE_;
            float q1  = qrow[NOPE_ + r];
            float rot = (r < 32) ? -qrow[NOPE_ + r + 32] : qrow[NOPE_ + r - 32];
            qv = q1 * cs[r] + rot * sn[r];
        }
        qf[dst] = to_tf32(qv * scale);
        float kvv;
        if (d < NOPE_) kvv = kv[(size_t)row * (H_ * 256) + h * 256 + d];
        else           kvv = kr[d - NOPE_];
        kf[dst] = to_tf32(kvv);
    }
    for (int idx = t; idx < H_ * VD_; idx += 256) {
        const int h  = idx >> 7;
        const int dv = idx & 127;
        v[((size_t)(b * H_ + h) * S_ + s) * VD_ + dv] =
            to_tf32(kv[(size_t)row * (H_ * 256) + h * 256 + NOPE_ + dv]);
    }
}

// ---------------------------------------------------------------------------
// Tensor-core causal flash attention (tf32 mma.sync) -- unchanged
// ---------------------------------------------------------------------------
constexpr int FK0 = 0;
constexpr int FV0 = 12544;
constexpr int FK1 = 21248;
constexpr int FV1 = 33792;
constexpr int FPS = 42496;
constexpr int FRM = 46848;
constexpr int FRS = 46976;
constexpr unsigned FL_SMEM_BYTES = 47104u * 4u;

__global__ __launch_bounds__(256, 1)
void flash_mma(const float* __restrict__ Qf, const float* __restrict__ Kf,
               const float* __restrict__ Vf, float* __restrict__ Out) {
    extern __shared__ float sm[];
    const uint32_t sb = smem_u32(sm);

    const int t    = threadIdx.x;
    const int wid  = t >> 5;
    const int lane = t & 31;
    const int g    = lane >> 2;
    const int tig  = lane & 3;
    const int wr   = wid >> 1;
    const int wc   = wid & 1;
    const int bh   = blockIdx.x;
    const int qt   = (int)gridDim.y - 1 - (int)blockIdx.y;
    const int q0   = qt * 64;
    const int b    = bh >> 4, h = bh & 15;

    const float* Kbase = Kf + (size_t)bh * S_ * QD_;
    const float* Vbase = Vf + (size_t)bh * S_ * VD_;

#define KV_LOAD(bufK, bufV, jj)                                                 \
    do {                                                                        \
        const float* Kb_ = Kbase + (size_t)(jj) * 64 * QD_;                     \
        const float* Vb_ = Vbase + (size_t)(jj) * 64 * VD_;                     \
        _Pragma("unroll")                                                       \
        for (int i_ = 0; i_ < 12; i_++) {                                       \
            const int f_ = t + i_ * 256;                                        \
            const int r_ = f_ / 48, c_ = (f_ % 48) * 4;                         \
            CPA16(sb + (uint32_t)((bufK) + r_ * 196 + c_) * 4u,                 \
                  Kb_ + r_ * QD_ + c_, 16);                                     \
        }                                                                       \
        _Pragma("unroll")                                                       \
        for (int i_ = 0; i_ < 8; i_++) {                                        \
            const int f_ = t + i_ * 256;                                        \
            const int r_ = f_ >> 5, c_ = (f_ & 31) * 4;                         \
            CPA16(sb + (uint32_t)((bufV) + r_ * 136 + c_) * 4u,                 \
                  Vb_ + r_ * VD_ + c_, 16);                                     \
        }                                                                       \
        asm volatile("cp.async.commit_group;" ::: "memory");                    \
    } while (0)

    {
        const float* Qb = Qf + ((size_t)bh * S_ + q0) * QD_;
#pragma unroll
        for (int i = 0; i < 12; i++) {
            const int f = t + i * 256;
            const int r = f / 48, c = (f % 48) * 4;
            CPA16(sb + (uint32_t)(FK1 + r * 196 + c) * 4u, Qb + r * QD_ + c, 16);
        }
        asm volatile("cp.async.commit_group;" ::: "memory");
    }
    KV_LOAD(FK0, FV0, 0);
    asm volatile("cp.async.wait_group 1;" ::: "memory");
    __syncthreads();

    uint32_t qr[24][4];
    {
        const float* Qs = sm + FK1 + (wr * 16 + g) * 196 + tig;
#pragma unroll
        for (int ks = 0; ks < 24; ks++) {
            qr[ks][0] = __float_as_uint(Qs[ks * 8]);
            qr[ks][1] = __float_as_uint(Qs[ks * 8 + 8 * 196]);
            qr[ks][2] = __float_as_uint(Qs[ks * 8 + 4]);
            qr[ks][3] = __float_as_uint(Qs[ks * 8 + 8 * 196 + 4]);
        }
    }
    __syncthreads();
    if (qt >= 1) KV_LOAD(FK1, FV1, 1);

    float mi0 = -INFINITY, mi1 = -INFINITY, li0 = 0.f, li1 = 0.f;
    float acc[8][4];
#pragma unroll
    for (int nt = 0; nt < 8; nt++)
#pragma unroll
        for (int c = 0; c < 4; c++) acc[nt][c] = 0.f;

    const int row0 = wr * 16 + g;
    const int row1 = row0 + 8;

    for (int j = 0; j <= qt; ++j) {
        if (j < qt) asm volatile("cp.async.wait_group 1;" ::: "memory");
        else        asm volatile("cp.async.wait_group 0;" ::: "memory");
        __syncthreads();

        const int KB = (j & 1) ? FK1 : FK0;
        const int VB = (j & 1) ? FV1 : FV0;

        float s4[4][4];
#pragma unroll
        for (int nt = 0; nt < 4; nt++)
#pragma unroll
            for (int c = 0; c < 4; c++) s4[nt][c] = 0.f;

#pragma unroll
        for (int ks = 0; ks < 24; ks++) {
            uint32_t bf[4][2];
#pragma unroll
            for (int nt = 0; nt < 4; nt++) {
                const float* kp = sm + KB + (wc * 32 + nt * 8 + g) * 196 + ks * 8 + tig;
                bf[nt][0] = __float_as_uint(kp[0]);
                bf[nt][1] = __float_as_uint(kp[4]);
            }
#pragma unroll
            for (int nt = 0; nt < 4; nt++)
                MMA_TF32(s4[nt], qr[ks], bf[nt]);
        }

        if (j == qt) {
#pragma unroll
            for (int nt = 0; nt < 4; nt++) {
                const int col = wc * 32 + nt * 8 + tig * 2;
                if (col     > row0) s4[nt][0] = -1e30f;
                if (col + 1 > row0) s4[nt][1] = -1e30f;
                if (col     > row1) s4[nt][2] = -1e30f;
                if (col + 1 > row1) s4[nt][3] = -1e30f;
            }
        }

        float pm0 = fmaxf(fmaxf(s4[0][0], s4[0][1]), fmaxf(s4[1][0], s4[1][1]));
        pm0 = fmaxf(pm0, fmaxf(fmaxf(s4[2][0], s4[2][1]), fmaxf(s4[3][0], s4[3][1])));
        float pm1 = fmaxf(fmaxf(s4[0][2], s4[0][3]), fmaxf(s4[1][2], s4[1][3]));
        pm1 = fmaxf(pm1, fmaxf(fmaxf(s4[2][2], s4[2][3]), fmaxf(s4[3][2], s4[3][3])));
        pm0 = fmaxf(pm0, __shfl_xor_sync(0xffffffffu, pm0, 1));
        pm0 = fmaxf(pm0, __shfl_xor_sync(0xffffffffu, pm0, 2));
        pm1 = fmaxf(pm1, __shfl_xor_sync(0xffffffffu, pm1, 1));
        pm1 = fmaxf(pm1, __shfl_xor_sync(0xffffffffu, pm1, 2));
        if (tig == 0) {
            sm[FRM + wc * 64 + row0] = pm0;
            sm[FRM + wc * 64 + row1] = pm1;
        }
        __syncthreads();
        const float rm0 = fmaxf(sm[FRM + row0], sm[FRM + 64 + row0]);
        const float rm1 = fmaxf(sm[FRM + row1], sm[FRM + 64 + row1]);
        const float mn0 = fmaxf(mi0, rm0), mn1 = fmaxf(mi1, rm1);
        const float corr0 = __expf(mi0 - mn0), corr1 = __expf(mi1 - mn1);
        mi0 = mn0; mi1 = mn1;

        float rs0 = 0.f, rs1 = 0.f;
#pragma unroll
        for (int nt = 0; nt < 4; nt++) {
            s4[nt][0] = __expf(s4[nt][0] - mn0); rs0 += s4[nt][0];
            s4[nt][1] = __expf(s4[nt][1] - mn0); rs0 += s4[nt][1];
            s4[nt][2] = __expf(s4[nt][2] - mn1); rs1 += s4[nt][2];
            s4[nt][3] = __expf(s4[nt][3] - mn1); rs1 += s4[nt][3];
        }
        rs0 += __shfl_xor_sync(0xffffffffu, rs0, 1);
        rs0 += __shfl_xor_sync(0xffffffffu, rs0, 2);
        rs1 += __shfl_xor_sync(0xffffffffu, rs1, 1);
        rs1 += __shfl_xor_sync(0xffffffffu, rs1, 2);
        if (tig == 0) {
            sm[FRS + wc * 64 + row0] = rs0;
            sm[FRS + wc * 64 + row1] = rs1;
        }
#pragma unroll
        for (int nt = 0; nt < 4; nt++) {
            const int col = wc * 32 + nt * 8 + tig * 2;
            *(float2*)&sm[FPS + row0 * 68 + col] =
                make_float2(to_tf32(s4[nt][0]), to_tf32(s4[nt][1]));
            *(float2*)&sm[FPS + row1 * 68 + col] =
                make_float2(to_tf32(s4[nt][2]), to_tf32(s4[nt][3]));
        }
        __syncthreads();

        li0 = li0 * corr0 + sm[FRS + row0] + sm[FRS + 64 + row0];
        li1 = li1 * corr1 + sm[FRS + row1] + sm[FRS + 64 + row1];
#pragma unroll
        for (int nt = 0; nt < 8; nt++) {
            acc[nt][0] *= corr0; acc[nt][1] *= corr0;
            acc[nt][2] *= corr1; acc[nt][3] *= corr1;
        }

#pragma unroll
        for (int ks = 0; ks < 8; ks++) {
            uint32_t a[4];
            const float* pp = sm + FPS + row0 * 68 + ks * 8 + tig;
            a[0] = __float_as_uint(pp[0]);
            a[1] = __float_as_uint(pp[8 * 68]);
            a[2] = __float_as_uint(pp[4]);
            a[3] = __float_as_uint(pp[8 * 68 + 4]);
#pragma unroll
            for (int nt = 0; nt < 8; nt++) {
                uint32_t bf[2];
                const float* vp = sm + VB + (ks * 8 + tig) * 136 + wc * 64 + nt * 8 + g;
                bf[0] = __float_as_uint(vp[0]);
                bf[1] = __float_as_uint(vp[4 * 136]);
                MMA_TF32(acc[nt], a, bf);
            }
        }
        __syncthreads();

        if (j + 2 <= qt) {
            if (j & 1) KV_LOAD(FK1, FV1, j + 2);
            else       KV_LOAD(FK0, FV0, j + 2);
        }
    }
#undef KV_LOAD

    const float linv0 = 1.0f / li0;
    const float linv1 = 1.0f / li1;
    const size_t r0g = (size_t)(b * S_ + q0 + row0) * (H_ * VD_) + h * VD_;
    const size_t r1g = (size_t)(b * S_ + q0 + row1) * (H_ * VD_) + h * VD_;
#pragma unroll
    for (int nt = 0; nt < 8; nt++) {
        const int col = wc * 64 + nt * 8 + tig * 2;
        *(float2*)&Out[r0g + col] =
            make_float2(to_tf32(acc[nt][0] * linv0), to_tf32(acc[nt][1] * linv0));
        *(float2*)&Out[r1g + col] =
            make_float2(to_tf32(acc[nt][2] * linv1), to_tf32(acc[nt][3] * linv1));
    }
}

// ---------------------------------------------------------------------------
// Launch
// ---------------------------------------------------------------------------
extern "C" void kernel_launch(void* const* d_in, const int* in_sizes, int n_in,
                              void* d_out, int out_size) {
    const float* x      = (const float*)d_in[0];
    const float* rope   = (const float*)d_in[1];
    const float* wq     = (const float*)d_in[2];
    const float* wkva   = (const float*)d_in[3];
    const float* norm_w = (const float*)d_in[4];
    const float* wkvb   = (const float*)d_in[5];
    const float* wo     = (const float*)d_in[6];
    float* out = (float*)d_out;

    float *p_qckv, *p_norm, *p_kv, *p_qf, *p_kf, *p_v, *p_attn;
    float *p_xr, *p_wqkva, *p_wkvbr, *p_wor;
    cudaGetSymbolAddress((void**)&p_qckv,  g_qckv);
    cudaGetSymbolAddress((void**)&p_norm,  g_norm);
    cudaGetSymbolAddress((void**)&p_kv,    g_kv);
    cudaGetSymbolAddress((void**)&p_qf,    g_qf);
    cudaGetSymbolAddress((void**)&p_kf,    g_kf);
    cudaGetSymbolAddress((void**)&p_v,     g_v);
    cudaGetSymbolAddress((void**)&p_attn,  g_attn);
    cudaGetSymbolAddress((void**)&p_xr,    g_xr);
    cudaGetSymbolAddress((void**)&p_wqkva, g_wqkva);
    cudaGetSymbolAddress((void**)&p_wkvbr, g_wkvbr);
    cudaGetSymbolAddress((void**)&p_wor,   g_wor);

    cudaFuncSetAttribute(mma_gemm, cudaFuncAttributeMaxDynamicSharedMemorySize,
                         MG_SMEM_BYTES);
    cudaFuncSetAttribute(flash_mma, cudaFuncAttributeMaxDynamicSharedMemorySize,
                         FL_SMEM_BYTES);

    // 0) round operands to tf32 (wq & wkva concatenated into fused B)
    {
        int n;
        n = BS_ * DIM_ / 4;
        round_tf32_kernel<<<1024, 256>>>((const float4*)x, (float4*)p_xr, n);
        n = H_ * QD_ * DIM_ / 4;
        round_tf32_kernel<<<1024, 256>>>((const float4*)wq, (float4*)p_wqkva, n);
        n = (KV_LORA_ + ROPE_) * DIM_ / 4;
        round_tf32_kernel<<<512, 256>>>((const float4*)wkva,
                                        (float4*)(p_wqkva + (size_t)H_ * QD_ * DIM_), n);
        n = H_ * 256 * KV_LORA_ / 4;
        round_tf32_kernel<<<512, 256>>>((const float4*)wkvb, (float4*)p_wkvbr, n);
        n = DIM_ * H_ * VD_ / 4;
        round_tf32_kernel<<<1024, 256>>>((const float4*)wo, (float4*)p_wor, n);
    }

    // 1) qckv = x @ [wq; wkva]^T   [4096, 3648]
    mma_gemm<<<dim3(15, 32), 256, MG_SMEM_BYTES>>>(p_xr, p_wqkva, p_qckv, NQC_, DIM_);
    // 2) RMSNorm
    rmsnorm_kernel<<<BS_, 128>>>(p_qckv, norm_w, p_norm);
    // 3) kv = norm @ wkvb^T        [4096, 4096]
    mma_gemm<<<dim3(16, 32), 256, MG_SMEM_BYTES>>>(p_norm, p_wkvbr, p_kv, H_ * 256, KV_LORA_);
    // 4) RoPE + assemble
    assemble_kernel<<<BS_, 256>>>(p_qckv, p_kv, rope, p_qf, p_kf, p_v);
    // 5) tensor-core causal flash attention
    flash_mma<<<dim3(B_ * H_, S_ / 64), 256, FL_SMEM_BYTES>>>(p_qf, p_kf, p_v, p_attn);
    // 6) out = attn @ wo^T         [4096, 2048]
    mma_gemm<<<dim3(8, 32), 256, MG_SMEM_BYTES>>>(p_attn, p_wor, out, DIM_, DIM_);
}

// round 14
// speedup vs baseline: 2.0358x; 2.0358x over previous
#include <cuda_runtime.h>
#include <cuda_bf16.h>
#include <math.h>
#include <stdint.h>

// Problem constants
#define B_       2
#define S_       2048
#define DIM_     2048
#define H_       16
#define KV_LORA_ 512
#define NOPE_    128
#define ROPE_    64
#define VD_      128
#define QD_      192
#define BS_      (B_ * S_)    // 4096
#define NQC_     3648         // fused q (3072) + ckv (576) output width

// ---------------------------------------------------------------------------
// Scratch
// ---------------------------------------------------------------------------
__device__ float g_qckv[BS_ * NQC_];           // fused q | ckv   (4096 x 3648)
__device__ float g_norm[BS_ * KV_LORA_];
__device__ float g_kv  [BS_ * H_ * (NOPE_ + VD_)];
__device__ float g_qf  [B_ * H_ * S_ * QD_];   // tf32-rounded, pre-scaled
__device__ float g_kf  [B_ * H_ * S_ * QD_];   // tf32-rounded
__device__ float g_v   [B_ * H_ * S_ * VD_];   // tf32-rounded
__device__ float g_attn[BS_ * H_ * VD_];       // tf32-rounded

__device__ float g_xr   [BS_ * DIM_];
__device__ float g_wqkva[NQC_ * DIM_];         // fused wq rows | wkva rows
__device__ float g_wkvbr[H_ * 256 * KV_LORA_];
__device__ float g_wor  [DIM_ * H_ * VD_];

// ---------------------------------------------------------------------------
// Helpers
// ---------------------------------------------------------------------------
__device__ __forceinline__ float to_tf32(float x) {
    uint32_t u;
    asm("cvt.rna.tf32.f32 %0, %1;" : "=r"(u) : "f"(x));
    return __uint_as_float(u);
}
__device__ __forceinline__ uint32_t smem_u32(const void* p) {
    uint32_t a;
    asm("{ .reg .u64 t; cvta.to.shared.u64 t, %1; cvt.u32.u64 %0, t; }"
        : "=r"(a) : "l"(p));
    return a;
}
#define CPA16(dst, src, sz) \
    asm volatile("cp.async.cg.shared.global [%0], [%1], 16, %2;" \
                 :: "r"(dst), "l"(src), "r"(sz) : "memory")
#define MMA_TF32(d, a, b)                                                     \
    asm volatile(                                                             \
        "mma.sync.aligned.m16n8k8.row.col.f32.tf32.tf32.f32 "                 \
        "{%0,%1,%2,%3}, {%4,%5,%6,%7}, {%8,%9}, {%0,%1,%2,%3};"               \
        : "+f"((d)[0]), "+f"((d)[1]), "+f"((d)[2]), "+f"((d)[3])              \
        : "r"((a)[0]), "r"((a)[1]), "r"((a)[2]), "r"((a)[3]),                 \
          "r"((b)[0]), "r"((b)[1]))

// ---------------------------------------------------------------------------
// tf32 mma.sync GEMM: C[M,N] = A[M,K] @ B[N,K]^T
// CTA tile 128x256, BK=32, 256 threads = 8 warps, warp tile 64x64,
// 4-stage cp.async pipeline, loads hoisted BEFORE compute (prefetch distance
// ~3 compute phases). 1 CTA/SM (register-bound); latency hidden by depth.
// M mult 128, K mult 32, N guarded.
// ---------------------------------------------------------------------------
constexpr int MG_STR    = 36;
constexpr int MG_ABUF   = 128 * MG_STR;            // 4608 floats
constexpr int MG_BBUF   = 256 * MG_STR;            // 9216 floats
constexpr int MG_STAGE  = MG_ABUF + MG_BBUF;       // 13824 floats
constexpr unsigned MG_SMEM_BYTES = 4u * MG_STAGE * sizeof(float);  // 221184

__global__ __launch_bounds__(256, 1)
void mma_gemm(const float* __restrict__ A, const float* __restrict__ Bm,
              float* __restrict__ C, int N, int K) {
    extern __shared__ float sm[];
    const uint32_t sb = smem_u32(sm);

    const int t    = threadIdx.x;
    const int wid  = t >> 5;
    const int lane = t & 31;
    const int g    = lane >> 2;
    const int tig  = lane & 3;
    const int wm   = (wid & 1) * 64;
    const int wn   = (wid >> 1) * 64;        // 0..192
    const int m0   = blockIdx.y * 128;
    const int n0   = blockIdx.x * 256;
    const int NK   = K / 32;

    // load coordinates: A = 1024 float4 (4/thread), B = 2048 float4 (8/thread)
    int arow[4], ac4[4];
    const float* Asrc[4];
#pragma unroll
    for (int j = 0; j < 4; j++) {
        const int f = t + j * 256;
        arow[j] = f >> 3;
        ac4[j]  = f & 7;
        Asrc[j] = A + (size_t)(m0 + arow[j]) * K + ac4[j] * 4;
    }
    int brow[8], bc4[8], bsz[8];
    const float* Bsrc[8];
#pragma unroll
    for (int j = 0; j < 8; j++) {
        const int f = t + j * 256;
        brow[j] = f >> 3;               // 0..255
        bc4[j]  = f & 7;
        const int gr = n0 + brow[j];
        bsz[j]  = (gr < N) ? 16 : 0;
        Bsrc[j] = Bm + (size_t)((gr < N) ? gr : 0) * K + bc4[j] * 4;
    }

#define MG_LOAD(stg, kc)                                                        \
    do {                                                                        \
        const int k0_ = (kc) * 32;                                              \
        const uint32_t sA_ = sb + (uint32_t)((stg) * MG_STAGE) * 4u;            \
        const uint32_t sB_ = sA_ + (uint32_t)MG_ABUF * 4u;                      \
        _Pragma("unroll")                                                       \
        for (int j = 0; j < 4; j++)                                             \
            CPA16(sA_ + (uint32_t)(arow[j] * MG_STR + ac4[j] * 4) * 4u,         \
                  Asrc[j] + k0_, 16);                                           \
        _Pragma("unroll")                                                       \
        for (int j = 0; j < 8; j++)                                             \
            CPA16(sB_ + (uint32_t)(brow[j] * MG_STR + bc4[j] * 4) * 4u,         \
                  Bsrc[j] + k0_, bsz[j]);                                       \
    } while (0)

    float acc[4][8][4];
#pragma unroll
    for (int mi = 0; mi < 4; mi++)
#pragma unroll
        for (int ni = 0; ni < 8; ni++)
#pragma unroll
            for (int c = 0; c < 4; c++) acc[mi][ni][c] = 0.0f;

    MG_LOAD(0, 0);
    asm volatile("cp.async.commit_group;" ::: "memory");
    MG_LOAD(1, 1);
    asm volatile("cp.async.commit_group;" ::: "memory");
    MG_LOAD(2, 2);
    asm volatile("cp.async.commit_group;" ::: "memory");

    for (int i = 0; i < NK; ++i) {
        const int cur = i & 3;
        asm volatile("cp.async.wait_group 2;" ::: "memory");
        __syncthreads();

        // Hoisted prefetch: stage (i+3)%4 == (i-1)%4, free after the sync above.
        if (i + 3 < NK) MG_LOAD((i + 3) & 3, i + 3);
        asm volatile("cp.async.commit_group;" ::: "memory");

        const float* Ab = sm + cur * MG_STAGE;
        const float* Bb = Ab + MG_ABUF;
#pragma unroll
        for (int ks = 0; ks < 4; ks++) {
            const int k0 = ks * 8;
            uint32_t a[4][4], b[8][2];
#pragma unroll
            for (int mi = 0; mi < 4; mi++) {
                const float* ap = Ab + (wm + mi * 16 + g) * MG_STR + k0 + tig;
                a[mi][0] = __float_as_uint(ap[0]);
                a[mi][1] = __float_as_uint(ap[8 * MG_STR]);
                a[mi][2] = __float_as_uint(ap[4]);
                a[mi][3] = __float_as_uint(ap[8 * MG_STR + 4]);
            }
#pragma unroll
            for (int ni = 0; ni < 8; ni++) {
                const float* bp = Bb + (wn + ni * 8 + g) * MG_STR + k0 + tig;
                b[ni][0] = __float_as_uint(bp[0]);
                b[ni][1] = __float_as_uint(bp[4]);
            }
#pragma unroll
            for (int mi = 0; mi < 4; mi++)
#pragma unroll
                for (int ni = 0; ni < 8; ni++)
                    MMA_TF32(acc[mi][ni], a[mi], b[ni]);
        }
    }
#undef MG_LOAD

#pragma unroll
    for (int mi = 0; mi < 4; mi++) {
        const int rr = m0 + wm + mi * 16 + g;
#pragma unroll
        for (int ni = 0; ni < 8; ni++) {
            const int cc = n0 + wn + ni * 8 + tig * 2;
            if (cc < N) {
                float2 v0 = make_float2(acc[mi][ni][0], acc[mi][ni][1]);
                float2 v1 = make_float2(acc[mi][ni][2], acc[mi][ni][3]);
                *(float2*)&C[(size_t)rr * N + cc]       = v0;
                *(float2*)&C[(size_t)(rr + 8) * N + cc] = v1;
            }
        }
    }
}

// ---------------------------------------------------------------------------
// tf32 rounding pass
// ---------------------------------------------------------------------------
__global__ __launch_bounds__(256) void round_tf32_kernel(const float4* __restrict__ src,
                                                         float4* __restrict__ dst, int n4) {
    for (int i = blockIdx.x * 256 + threadIdx.x; i < n4; i += gridDim.x * 256) {
        float4 v = src[i];
        v.x = to_tf32(v.x); v.y = to_tf32(v.y);
        v.z = to_tf32(v.z); v.w = to_tf32(v.w);
        dst[i] = v;
    }
}

// ---------------------------------------------------------------------------
// RMSNorm over qckv[row, 3072:3584]; tf32-rounded out
// ---------------------------------------------------------------------------
__global__ __launch_bounds__(128) void rmsnorm_kernel(const float* __restrict__ qckv,
                                                      const float* __restrict__ w,
                                                      float* __restrict__ outp) {
    const int row = blockIdx.x;
    const int t   = threadIdx.x;
    const float* xr = qckv + (size_t)row * NQC_ + H_ * QD_;
    float v[4];
    float s = 0.f;
#pragma unroll
    for (int i = 0; i < 4; i++) { v[i] = xr[t + i * 128]; s += v[i] * v[i]; }
#pragma unroll
    for (int m = 16; m >= 1; m >>= 1) s += __shfl_xor_sync(0xffffffffu, s, m);
    __shared__ float ws[4];
    if ((t & 31) == 0) ws[t >> 5] = s;
    __syncthreads();
    s = ws[0] + ws[1] + ws[2] + ws[3];
    const float inv = rsqrtf(s * (1.0f / (float)KV_LORA_) + 1e-6f);
    float* orow = outp + (size_t)row * KV_LORA_;
#pragma unroll
    for (int i = 0; i < 4; i++) orow[t + i * 128] = to_tf32(v[i] * inv * w[t + i * 128]);
}

// ---------------------------------------------------------------------------
// RoPE + assembly from fused qckv; outputs tf32-rounded
// ---------------------------------------------------------------------------
__global__ __launch_bounds__(256) void assemble_kernel(const float* __restrict__ qckv,
                                                       const float* __restrict__ kv,
                                                       const float* __restrict__ rope,
                                                       float* __restrict__ qf,
                                                       float* __restrict__ kf,
                                                       float* __restrict__ v) {
    const int row = blockIdx.x;
    const int s   = row & (S_ - 1);
    const int b   = row >> 11;
    const int t   = threadIdx.x;

    __shared__ float cs[64], sn[64], kr[64];
    if (t < 64) {
        cs[t] = rope[(size_t)s * 128 + t];
        sn[t] = rope[(size_t)s * 128 + 64 + t];
    }
    __syncthreads();
    if (t < 64) {
        const float* cr = qckv + (size_t)row * NQC_ + H_ * QD_ + KV_LORA_;
        float k0  = cr[t];
        float rot = (t < 32) ? -cr[t + 32] : cr[t - 32];
        kr[t] = k0 * cs[t] + rot * sn[t];
    }
    __syncthreads();

    const float scale = rsqrtf((float)QD_);
    for (int idx = t; idx < H_ * QD_; idx += 256) {
        const int h = idx / QD_;
        const int d = idx - h * QD_;
        const size_t dst = ((size_t)(b * H_ + h) * S_ + s) * QD_ + d;
        const float* qrow = qckv + (size_t)row * NQC_ + h * QD_;
        float qv;
        if (d < NOPE_) {
            qv = qrow[d];
        } else {
            const int r   = d - NOPE_;
            float q1  = qrow[NOPE_ + r];
            float rot = (r < 32) ? -qrow[NOPE_ + r + 32] : qrow[NOPE_ + r - 32];
            qv = q1 * cs[r] + rot * sn[r];
        }
        qf[dst] = to_tf32(qv * scale);
        float kvv;
        if (d < NOPE_) kvv = kv[(size_t)row * (H_ * 256) + h * 256 + d];
        else           kvv = kr[d - NOPE_];
        kf[dst] = to_tf32(kvv);
    }
    for (int idx = t; idx < H_ * VD_; idx += 256) {
        const int h  = idx >> 7;
        const int dv = idx & 127;
        v[((size_t)(b * H_ + h) * S_ + s) * VD_ + dv] =
            to_tf32(kv[(size_t)row * (H_ * 256) + h * 256 + NOPE_ + dv]);
    }
}

// ---------------------------------------------------------------------------
// Tensor-core causal flash attention (tf32 mma.sync) -- unchanged
// ---------------------------------------------------------------------------
constexpr int FK0 = 0;
constexpr int FV0 = 12544;
constexpr int FK1 = 21248;
constexpr int FV1 = 33792;
constexpr int FPS = 42496;
constexpr int FRM = 46848;
constexpr int FRS = 46976;
constexpr unsigned FL_SMEM_BYTES = 47104u * 4u;

__global__ __launch_bounds__(256, 1)
void flash_mma(const float* __restrict__ Qf, const float* __restrict__ Kf,
               const float* __restrict__ Vf, float* __restrict__ Out) {
    extern __shared__ float sm[];
    const uint32_t sb = smem_u32(sm);

    const int t    = threadIdx.x;
    const int wid  = t >> 5;
    const int lane = t & 31;
    const int g    = lane >> 2;
    const int tig  = lane & 3;
    const int wr   = wid >> 1;
    const int wc   = wid & 1;
    const int bh   = blockIdx.x;
    const int qt   = (int)gridDim.y - 1 - (int)blockIdx.y;
    const int q0   = qt * 64;
    const int b    = bh >> 4, h = bh & 15;

    const float* Kbase = Kf + (size_t)bh * S_ * QD_;
    const float* Vbase = Vf + (size_t)bh * S_ * VD_;

#define KV_LOAD(bufK, bufV, jj)                                                 \
    do {                                                                        \
        const float* Kb_ = Kbase + (size_t)(jj) * 64 * QD_;                     \
        const float* Vb_ = Vbase + (size_t)(jj) * 64 * VD_;                     \
        _Pragma("unroll")                                                       \
        for (int i_ = 0; i_ < 12; i_++) {                                       \
            const int f_ = t + i_ * 256;                                        \
            const int r_ = f_ / 48, c_ = (f_ % 48) * 4;                         \
            CPA16(sb + (uint32_t)((bufK) + r_ * 196 + c_) * 4u,                 \
                  Kb_ + r_ * QD_ + c_, 16);                                     \
        }                                                                       \
        _Pragma("unroll")                                                       \
        for (int i_ = 0; i_ < 8; i_++) {                                        \
            const int f_ = t + i_ * 256;                                        \
            const int r_ = f_ >> 5, c_ = (f_ & 31) * 4;                         \
            CPA16(sb + (uint32_t)((bufV) + r_ * 136 + c_) * 4u,                 \
                  Vb_ + r_ * VD_ + c_, 16);                                     \
        }                                                                       \
        asm volatile("cp.async.commit_group;" ::: "memory");                    \
    } while (0)

    {
        const float* Qb = Qf + ((size_t)bh * S_ + q0) * QD_;
#pragma unroll
        for (int i = 0; i < 12; i++) {
            const int f = t + i * 256;
            const int r = f / 48, c = (f % 48) * 4;
            CPA16(sb + (uint32_t)(FK1 + r * 196 + c) * 4u, Qb + r * QD_ + c, 16);
        }
        asm volatile("cp.async.commit_group;" ::: "memory");
    }
    KV_LOAD(FK0, FV0, 0);
    asm volatile("cp.async.wait_group 1;" ::: "memory");
    __syncthreads();

    uint32_t qr[24][4];
    {
        const float* Qs = sm + FK1 + (wr * 16 + g) * 196 + tig;
#pragma unroll
        for (int ks = 0; ks < 24; ks++) {
            qr[ks][0] = __float_as_uint(Qs[ks * 8]);
            qr[ks][1] = __float_as_uint(Qs[ks * 8 + 8 * 196]);
            qr[ks][2] = __float_as_uint(Qs[ks * 8 + 4]);
            qr[ks][3] = __float_as_uint(Qs[ks * 8 + 8 * 196 + 4]);
        }
    }
    __syncthreads();
    if (qt >= 1) KV_LOAD(FK1, FV1, 1);

    float mi0 = -INFINITY, mi1 = -INFINITY, li0 = 0.f, li1 = 0.f;
    float acc[8][4];
#pragma unroll
    for (int nt = 0; nt < 8; nt++)
#pragma unroll
        for (int c = 0; c < 4; c++) acc[nt][c] = 0.f;

    const int row0 = wr * 16 + g;
    const int row1 = row0 + 8;

    for (int j = 0; j <= qt; ++j) {
        if (j < qt) asm volatile("cp.async.wait_group 1;" ::: "memory");
        else        asm volatile("cp.async.wait_group 0;" ::: "memory");
        __syncthreads();

        const int KB = (j & 1) ? FK1 : FK0;
        const int VB = (j & 1) ? FV1 : FV0;

        float s4[4][4];
#pragma unroll
        for (int nt = 0; nt < 4; nt++)
#pragma unroll
            for (int c = 0; c < 4; c++) s4[nt][c] = 0.f;

#pragma unroll
        for (int ks = 0; ks < 24; ks++) {
            uint32_t bf[4][2];
#pragma unroll
            for (int nt = 0; nt < 4; nt++) {
                const float* kp = sm + KB + (wc * 32 + nt * 8 + g) * 196 + ks * 8 + tig;
                bf[nt][0] = __float_as_uint(kp[0]);
                bf[nt][1] = __float_as_uint(kp[4]);
            }
#pragma unroll
            for (int nt = 0; nt < 4; nt++)
                MMA_TF32(s4[nt], qr[ks], bf[nt]);
        }

        if (j == qt) {
#pragma unroll
            for (int nt = 0; nt < 4; nt++) {
                const int col = wc * 32 + nt * 8 + tig * 2;
                if (col     > row0) s4[nt][0] = -1e30f;
                if (col + 1 > row0) s4[nt][1] = -1e30f;
                if (col     > row1) s4[nt][2] = -1e30f;
                if (col + 1 > row1) s4[nt][3] = -1e30f;
            }
        }

        float pm0 = fmaxf(fmaxf(s4[0][0], s4[0][1]), fmaxf(s4[1][0], s4[1][1]));
        pm0 = fmaxf(pm0, fmaxf(fmaxf(s4[2][0], s4[2][1]), fmaxf(s4[3][0], s4[3][1])));
        float pm1 = fmaxf(fmaxf(s4[0][2], s4[0][3]), fmaxf(s4[1][2], s4[1][3]));
        pm1 = fmaxf(pm1, fmaxf(fmaxf(s4[2][2], s4[2][3]), fmaxf(s4[3][2], s4[3][3])));
        pm0 = fmaxf(pm0, __shfl_xor_sync(0xffffffffu, pm0, 1));
        pm0 = fmaxf(pm0, __shfl_xor_sync(0xffffffffu, pm0, 2));
        pm1 = fmaxf(pm1, __shfl_xor_sync(0xffffffffu, pm1, 1));
        pm1 = fmaxf(pm1, __shfl_xor_sync(0xffffffffu, pm1, 2));
        if (tig == 0) {
            sm[FRM + wc * 64 + row0] = pm0;
            sm[FRM + wc * 64 + row1] = pm1;
        }
        __syncthreads();
        const float rm0 = fmaxf(sm[FRM + row0], sm[FRM + 64 + row0]);
        const float rm1 = fmaxf(sm[FRM + row1], sm[FRM + 64 + row1]);
        const float mn0 = fmaxf(mi0, rm0), mn1 = fmaxf(mi1, rm1);
        const float corr0 = __expf(mi0 - mn0), corr1 = __expf(mi1 - mn1);
        mi0 = mn0; mi1 = mn1;

        float rs0 = 0.f, rs1 = 0.f;
#pragma unroll
        for (int nt = 0; nt < 4; nt++) {
            s4[nt][0] = __expf(s4[nt][0] - mn0); rs0 += s4[nt][0];
            s4[nt][1] = __expf(s4[nt][1] - mn0); rs0 += s4[nt][1];
            s4[nt][2] = __expf(s4[nt][2] - mn1); rs1 += s4[nt][2];
            s4[nt][3] = __expf(s4[nt][3] - mn1); rs1 += s4[nt][3];
        }
        rs0 += __shfl_xor_sync(0xffffffffu, rs0, 1);
        rs0 += __shfl_xor_sync(0xffffffffu, rs0, 2);
        rs1 += __shfl_xor_sync(0xffffffffu, rs1, 1);
        rs1 += __shfl_xor_sync(0xffffffffu, rs1, 2);
        if (tig == 0) {
            sm[FRS + wc * 64 + row0] = rs0;
            sm[FRS + wc * 64 + row1] = rs1;
        }
#pragma unroll
        for (int nt = 0; nt < 4; nt++) {
            const int col = wc * 32 + nt * 8 + tig * 2;
            *(float2*)&sm[FPS + row0 * 68 + col] =
                make_float2(to_tf32(s4[nt][0]), to_tf32(s4[nt][1]));
            *(float2*)&sm[FPS + row1 * 68 + col] =
                make_float2(to_tf32(s4[nt][2]), to_tf32(s4[nt][3]));
        }
        __syncthreads();

        li0 = li0 * corr0 + sm[FRS + row0] + sm[FRS + 64 + row0];
        li1 = li1 * corr1 + sm[FRS + row1] + sm[FRS + 64 + row1];
#pragma unroll
        for (int nt = 0; nt < 8; nt++) {
            acc[nt][0] *= corr0; acc[nt][1] *= corr0;
            acc[nt][2] *= corr1; acc[nt][3] *= corr1;
        }

#pragma unroll
        for (int ks = 0; ks < 8; ks++) {
            uint32_t a[4];
            const float* pp = sm + FPS + row0 * 68 + ks * 8 + tig;
            a[0] = __float_as_uint(pp[0]);
            a[1] = __float_as_uint(pp[8 * 68]);
            a[2] = __float_as_uint(pp[4]);
            a[3] = __float_as_uint(pp[8 * 68 + 4]);
#pragma unroll
            for (int nt = 0; nt < 8; nt++) {
                uint32_t bf[2];
                const float* vp = sm + VB + (ks * 8 + tig) * 136 + wc * 64 + nt * 8 + g;
                bf[0] = __float_as_uint(vp[0]);
                bf[1] = __float_as_uint(vp[4 * 136]);
                MMA_TF32(acc[nt], a, bf);
            }
        }
        __syncthreads();

        if (j + 2 <= qt) {
            if (j & 1) KV_LOAD(FK1, FV1, j + 2);
            else       KV_LOAD(FK0, FV0, j + 2);
        }
    }
#undef KV_LOAD

    const float linv0 = 1.0f / li0;
    const float linv1 = 1.0f / li1;
    const size_t r0g = (size_t)(b * S_ + q0 + row0) * (H_ * VD_) + h * VD_;
    const size_t r1g = (size_t)(b * S_ + q0 + row1) * (H_ * VD_) + h * VD_;
#pragma unroll
    for (int nt = 0; nt < 8; nt++) {
        const int col = wc * 64 + nt * 8 + tig * 2;
        *(float2*)&Out[r0g + col] =
            make_float2(to_tf32(acc[nt][0] * linv0), to_tf32(acc[nt][1] * linv0));
        *(float2*)&Out[r1g + col] =
            make_float2(to_tf32(acc[nt][2] * linv1), to_tf32(acc[nt][3] * linv1));
    }
}

// ---------------------------------------------------------------------------
// Launch
// ---------------------------------------------------------------------------
extern "C" void kernel_launch(void* const* d_in, const int* in_sizes, int n_in,
                              void* d_out, int out_size) {
    const float* x      = (const float*)d_in[0];
    const float* rope   = (const float*)d_in[1];
    const float* wq     = (const float*)d_in[2];
    const float* wkva   = (const float*)d_in[3];
    const float* norm_w = (const float*)d_in[4];
    const float* wkvb   = (const float*)d_in[5];
    const float* wo     = (const float*)d_in[6];
    float* out = (float*)d_out;

    float *p_qckv, *p_norm, *p_kv, *p_qf, *p_kf, *p_v, *p_attn;
    float *p_xr, *p_wqkva, *p_wkvbr, *p_wor;
    cudaGetSymbolAddress((void**)&p_qckv,  g_qckv);
    cudaGetSymbolAddress((void**)&p_norm,  g_norm);
    cudaGetSymbolAddress((void**)&p_kv,    g_kv);
    cudaGetSymbolAddress((void**)&p_qf,    g_qf);
    cudaGetSymbolAddress((void**)&p_kf,    g_kf);
    cudaGetSymbolAddress((void**)&p_v,     g_v);
    cudaGetSymbolAddress((void**)&p_attn,  g_attn);
    cudaGetSymbolAddress((void**)&p_xr,    g_xr);
    cudaGetSymbolAddress((void**)&p_wqkva, g_wqkva);
    cudaGetSymbolAddress((void**)&p_wkvbr, g_wkvbr);
    cudaGetSymbolAddress((void**)&p_wor,   g_wor);

    cudaFuncSetAttribute(mma_gemm, cudaFuncAttributeMaxDynamicSharedMemorySize,
                         MG_SMEM_BYTES);
    cudaFuncSetAttribute(flash_mma, cudaFuncAttributeMaxDynamicSharedMemorySize,
                         FL_SMEM_BYTES);

    // 0) round operands to tf32 (wq & wkva concatenated into fused B)
    {
        int n;
        n = BS_ * DIM_ / 4;
        round_tf32_kernel<<<1024, 256>>>((const float4*)x, (float4*)p_xr, n);
        n = H_ * QD_ * DIM_ / 4;
        round_tf32_kernel<<<1024, 256>>>((const float4*)wq, (float4*)p_wqkva, n);
        n = (KV_LORA_ + ROPE_) * DIM_ / 4;
        round_tf32_kernel<<<512, 256>>>((const float4*)wkva,
                                        (float4*)(p_wqkva + (size_t)H_ * QD_ * DIM_), n);
        n = H_ * 256 * KV_LORA_ / 4;
        round_tf32_kernel<<<512, 256>>>((const float4*)wkvb, (float4*)p_wkvbr, n);
        n = DIM_ * H_ * VD_ / 4;
        round_tf32_kernel<<<1024, 256>>>((const float4*)wo, (float4*)p_wor, n);
    }

    // 1) qckv = x @ [wq; wkva]^T   [4096, 3648]
    mma_gemm<<<dim3(15, 32), 256, MG_SMEM_BYTES>>>(p_xr, p_wqkva, p_qckv, NQC_, DIM_);
    // 2) RMSNorm
    rmsnorm_kernel<<<BS_, 128>>>(p_qckv, norm_w, p_norm);
    // 3) kv = norm @ wkvb^T        [4096, 4096]
    mma_gemm<<<dim3(16, 32), 256, MG_SMEM_BYTES>>>(p_norm, p_wkvbr, p_kv, H_ * 256, KV_LORA_);
    // 4) RoPE + assemble
    assemble_kernel<<<BS_, 256>>>(p_qckv, p_kv, rope, p_qf, p_kf, p_v);
    // 5) tensor-core causal flash attention
    flash_mma<<<dim3(B_ * H_, S_ / 64), 256, FL_SMEM_BYTES>>>(p_qf, p_kf, p_v, p_attn);
    // 6) out = attn @ wo^T         [4096, 2048]
    mma_gemm<<<dim3(8, 32), 256, MG_SMEM_BYTES>>>(p_attn, p_wor, out, DIM_, DIM_);
}

// round 16
// speedup vs baseline: 2.1781x; 1.0699x over previous
#include <cuda_runtime.h>
#include <cuda_bf16.h>
#include <math.h>
#include <stdint.h>

// Problem constants
#define B_       2
#define S_       2048
#define DIM_     2048
#define H_       16
#define KV_LORA_ 512
#define NOPE_    128
#define ROPE_    64
#define VD_      128
#define QD_      192
#define BS_      (B_ * S_)    // 4096
#define NQC_     3648         // fused q (3072) + ckv (576) output width

// ---------------------------------------------------------------------------
// Scratch
// ---------------------------------------------------------------------------
__device__ float g_qckv[BS_ * NQC_];
__device__ float g_norm[BS_ * KV_LORA_];
__device__ float g_kv  [BS_ * H_ * (NOPE_ + VD_)];
__device__ float g_qf  [B_ * H_ * S_ * QD_];
__device__ float g_kf  [B_ * H_ * S_ * QD_];
__device__ float g_v   [B_ * H_ * S_ * VD_];
__device__ float g_attn[BS_ * H_ * VD_];

__device__ float g_xr   [BS_ * DIM_];
__device__ float g_wqkva[NQC_ * DIM_];
__device__ float g_wkvbr[H_ * 256 * KV_LORA_];
__device__ float g_wor  [DIM_ * H_ * VD_];

// ---------------------------------------------------------------------------
// Helpers
// ---------------------------------------------------------------------------
__device__ __forceinline__ float to_tf32(float x) {
    uint32_t u;
    asm("cvt.rna.tf32.f32 %0, %1;" : "=r"(u) : "f"(x));
    return __uint_as_float(u);
}
__device__ __forceinline__ uint32_t smem_u32(const void* p) {
    uint32_t a;
    asm("{ .reg .u64 t; cvta.to.shared.u64 t, %1; cvt.u32.u64 %0, t; }"
        : "=r"(a) : "l"(p));
    return a;
}
#define CPA16(dst, src, sz) \
    asm volatile("cp.async.cg.shared.global [%0], [%1], 16, %2;" \
                 :: "r"(dst), "l"(src), "r"(sz) : "memory")
#define MMA_TF32(d, a, b)                                                     \
    asm volatile(                                                             \
        "mma.sync.aligned.m16n8k8.row.col.f32.tf32.tf32.f32 "                 \
        "{%0,%1,%2,%3}, {%4,%5,%6,%7}, {%8,%9}, {%0,%1,%2,%3};"               \
        : "+f"((d)[0]), "+f"((d)[1]), "+f"((d)[2]), "+f"((d)[3])              \
        : "r"((a)[0]), "r"((a)[1]), "r"((a)[2]), "r"((a)[3]),                 \
          "r"((b)[0]), "r"((b)[1]))

// ---------------------------------------------------------------------------
// tf32 mma.sync GEMM (R12-proven mainloop): C[M,N] = A[M,K] @ B[N,K]^T
// CTA 128x256, BK=32, 256 threads = 8 warps, warp tile 64x64, 3-stage.
// n_off shifts the N-tile origin (for split launches over one C buffer).
// ---------------------------------------------------------------------------
constexpr int MG_STR    = 36;
constexpr int MG_ABUF   = 128 * MG_STR;
constexpr int MG_BBUF   = 256 * MG_STR;
constexpr int MG_STAGE  = MG_ABUF + MG_BBUF;       // 13824 floats
constexpr unsigned MG_SMEM_BYTES = 3u * MG_STAGE * sizeof(float);  // 165888

__global__ __launch_bounds__(256, 1)
void mma_gemm(const float* __restrict__ A, const float* __restrict__ Bm,
              float* __restrict__ C, int N, int K, int n_off) {
    extern __shared__ float sm[];
    const uint32_t sb = smem_u32(sm);

    const int t    = threadIdx.x;
    const int wid  = t >> 5;
    const int lane = t & 31;
    const int g    = lane >> 2;
    const int tig  = lane & 3;
    const int wm   = (wid & 1) * 64;
    const int wn   = (wid >> 1) * 64;
    const int m0   = blockIdx.y * 128;
    const int n0   = (blockIdx.x + n_off) * 256;
    const int NK   = K / 32;

    int arow[4], ac4[4];
    const float* Asrc[4];
#pragma unroll
    for (int j = 0; j < 4; j++) {
        const int f = t + j * 256;
        arow[j] = f >> 3;
        ac4[j]  = f & 7;
        Asrc[j] = A + (size_t)(m0 + arow[j]) * K + ac4[j] * 4;
    }
    int brow[8], bc4[8], bsz[8];
    const float* Bsrc[8];
#pragma unroll
    for (int j = 0; j < 8; j++) {
        const int f = t + j * 256;
        brow[j] = f >> 3;
        bc4[j]  = f & 7;
        const int gr = n0 + brow[j];
        bsz[j]  = (gr < N) ? 16 : 0;
        Bsrc[j] = Bm + (size_t)((gr < N) ? gr : 0) * K + bc4[j] * 4;
    }

#define MG_LOAD(stg, kc)                                                        \
    do {                                                                        \
        const int k0_ = (kc) * 32;                                              \
        const uint32_t sA_ = sb + (uint32_t)((stg) * MG_STAGE) * 4u;            \
        const uint32_t sB_ = sA_ + (uint32_t)MG_ABUF * 4u;                      \
        _Pragma("unroll")                                                       \
        for (int j = 0; j < 4; j++)                                             \
            CPA16(sA_ + (uint32_t)(arow[j] * MG_STR + ac4[j] * 4) * 4u,         \
                  Asrc[j] + k0_, 16);                                           \
        _Pragma("unroll")                                                       \
        for (int j = 0; j < 8; j++)                                             \
            CPA16(sB_ + (uint32_t)(brow[j] * MG_STR + bc4[j] * 4) * 4u,         \
                  Bsrc[j] + k0_, bsz[j]);                                       \
    } while (0)

    float acc[4][8][4];
#pragma unroll
    for (int mi = 0; mi < 4; mi++)
#pragma unroll
        for (int ni = 0; ni < 8; ni++)
#pragma unroll
            for (int c = 0; c < 4; c++) acc[mi][ni][c] = 0.0f;

    MG_LOAD(0, 0);
    asm volatile("cp.async.commit_group;" ::: "memory");
    MG_LOAD(1, 1);
    asm volatile("cp.async.commit_group;" ::: "memory");

    int stg = 0;
    for (int i = 0; i < NK; ++i) {
        asm volatile("cp.async.wait_group 1;" ::: "memory");
        __syncthreads();

        const float* Ab = sm + stg * MG_STAGE;
        const float* Bb = Ab + MG_ABUF;
#pragma unroll
        for (int ks = 0; ks < 4; ks++) {
            const int k0 = ks * 8;
            uint32_t a[4][4], b[8][2];
#pragma unroll
            for (int mi = 0; mi < 4; mi++) {
                const float* ap = Ab + (wm + mi * 16 + g) * MG_STR + k0 + tig;
                a[mi][0] = __float_as_uint(ap[0]);
                a[mi][1] = __float_as_uint(ap[8 * MG_STR]);
                a[mi][2] = __float_as_uint(ap[4]);
                a[mi][3] = __float_as_uint(ap[8 * MG_STR + 4]);
            }
#pragma unroll
            for (int ni = 0; ni < 8; ni++) {
                const float* bp = Bb + (wn + ni * 8 + g) * MG_STR + k0 + tig;
                b[ni][0] = __float_as_uint(bp[0]);
                b[ni][1] = __float_as_uint(bp[4]);
            }
#pragma unroll
            for (int mi = 0; mi < 4; mi++)
#pragma unroll
                for (int ni = 0; ni < 8; ni++)
                    MMA_TF32(acc[mi][ni], a[mi], b[ni]);
        }

        if (i + 2 < NK) MG_LOAD((stg + 2) % 3, i + 2);
        asm volatile("cp.async.commit_group;" ::: "memory");
        stg = (stg + 1) % 3;
    }
#undef MG_LOAD

#pragma unroll
    for (int mi = 0; mi < 4; mi++) {
        const int rr = m0 + wm + mi * 16 + g;
#pragma unroll
        for (int ni = 0; ni < 8; ni++) {
            const int cc = n0 + wn + ni * 8 + tig * 2;
            if (cc < N) {
                float2 v0 = make_float2(acc[mi][ni][0], acc[mi][ni][1]);
                float2 v1 = make_float2(acc[mi][ni][2], acc[mi][ni][3]);
                *(float2*)&C[(size_t)rr * N + cc]       = v0;
                *(float2*)&C[(size_t)(rr + 8) * N + cc] = v1;
            }
        }
    }
}

// ---------------------------------------------------------------------------
// tf32 rounding passes
// ---------------------------------------------------------------------------
__global__ __launch_bounds__(256) void round_tf32_kernel(const float4* __restrict__ src,
                                                         float4* __restrict__ dst, int n4) {
    for (int i = blockIdx.x * 256 + threadIdx.x; i < n4; i += gridDim.x * 256) {
        float4 v = src[i];
        v.x = to_tf32(v.x); v.y = to_tf32(v.y);
        v.z = to_tf32(v.z); v.w = to_tf32(v.w);
        dst[i] = v;
    }
}

// fused 3-tensor rounding (wkva | wkvb | wo)
__global__ __launch_bounds__(256) void round3_kernel(
    const float4* __restrict__ s1, float4* __restrict__ d1, int n1,
    const float4* __restrict__ s2, float4* __restrict__ d2, int n2,
    const float4* __restrict__ s3, float4* __restrict__ d3, int n3) {
    const int total = n1 + n2 + n3;
    for (int i = blockIdx.x * 256 + threadIdx.x; i < total; i += gridDim.x * 256) {
        const float4* sp;
        float4* dp;
        int k;
        if (i < n1)            { sp = s1; dp = d1; k = i; }
        else if (i < n1 + n2)  { sp = s2; dp = d2; k = i - n1; }
        else                   { sp = s3; dp = d3; k = i - n1 - n2; }
        float4 v = sp[k];
        v.x = to_tf32(v.x); v.y = to_tf32(v.y);
        v.z = to_tf32(v.z); v.w = to_tf32(v.w);
        dp[k] = v;
    }
}

// ---------------------------------------------------------------------------
// RMSNorm over qckv[row, 3072:3584]; tf32-rounded out
// ---------------------------------------------------------------------------
__global__ __launch_bounds__(128) void rmsnorm_kernel(const float* __restrict__ qckv,
                                                      const float* __restrict__ w,
                                                      float* __restrict__ outp) {
    const int row = blockIdx.x;
    const int t   = threadIdx.x;
    const float* xr = qckv + (size_t)row * NQC_ + H_ * QD_;
    float v[4];
    float s = 0.f;
#pragma unroll
    for (int i = 0; i < 4; i++) { v[i] = xr[t + i * 128]; s += v[i] * v[i]; }
#pragma unroll
    for (int m = 16; m >= 1; m >>= 1) s += __shfl_xor_sync(0xffffffffu, s, m);
    __shared__ float ws[4];
    if ((t & 31) == 0) ws[t >> 5] = s;
    __syncthreads();
    s = ws[0] + ws[1] + ws[2] + ws[3];
    const float inv = rsqrtf(s * (1.0f / (float)KV_LORA_) + 1e-6f);
    float* orow = outp + (size_t)row * KV_LORA_;
#pragma unroll
    for (int i = 0; i < 4; i++) orow[t + i * 128] = to_tf32(v[i] * inv * w[t + i * 128]);
}

// ---------------------------------------------------------------------------
// RoPE + assembly from fused qckv; outputs tf32-rounded
// ---------------------------------------------------------------------------
__global__ __launch_bounds__(256) void assemble_kernel(const float* __restrict__ qckv,
                                                       const float* __restrict__ kv,
                                                       const float* __restrict__ rope,
                                                       float* __restrict__ qf,
                                                       float* __restrict__ kf,
                                                       float* __restrict__ v) {
    const int row = blockIdx.x;
    const int s   = row & (S_ - 1);
    const int b   = row >> 11;
    const int t   = threadIdx.x;

    __shared__ float cs[64], sn[64], kr[64];
    if (t < 64) {
        cs[t] = rope[(size_t)s * 128 + t];
        sn[t] = rope[(size_t)s * 128 + 64 + t];
    }
    __syncthreads();
    if (t < 64) {
        const float* cr = qckv + (size_t)row * NQC_ + H_ * QD_ + KV_LORA_;
        float k0  = cr[t];
        float rot = (t < 32) ? -cr[t + 32] : cr[t - 32];
        kr[t] = k0 * cs[t] + rot * sn[t];
    }
    __syncthreads();

    const float scale = rsqrtf((float)QD_);
    for (int idx = t; idx < H_ * QD_; idx += 256) {
        const int h = idx / QD_;
        const int d = idx - h * QD_;
        const size_t dst = ((size_t)(b * H_ + h) * S_ + s) * QD_ + d;
        const float* qrow = qckv + (size_t)row * NQC_ + h * QD_;
        float qv;
        if (d < NOPE_) {
            qv = qrow[d];
        } else {
            const int r   = d - NOPE_;
            float q1  = qrow[NOPE_ + r];
            float rot = (r < 32) ? -qrow[NOPE_ + r + 32] : qrow[NOPE_ + r - 32];
            qv = q1 * cs[r] + rot * sn[r];
        }
        qf[dst] = to_tf32(qv * scale);
        float kvv;
        if (d < NOPE_) kvv = kv[(size_t)row * (H_ * 256) + h * 256 + d];
        else           kvv = kr[d - NOPE_];
        kf[dst] = to_tf32(kvv);
    }
    for (int idx = t; idx < H_ * VD_; idx += 256) {
        const int h  = idx >> 7;
        const int dv = idx & 127;
        v[((size_t)(b * H_ + h) * S_ + s) * VD_ + dv] =
            to_tf32(kv[(size_t)row * (H_ * 256) + h * 256 + NOPE_ + dv]);
    }
}

// ---------------------------------------------------------------------------
// Tensor-core causal flash attention (tf32 mma.sync) -- unchanged
// ---------------------------------------------------------------------------
constexpr int FK0 = 0;
constexpr int FV0 = 12544;
constexpr int FK1 = 21248;
constexpr int FV1 = 33792;
constexpr int FPS = 42496;
constexpr int FRM = 46848;
constexpr int FRS = 46976;
constexpr unsigned FL_SMEM_BYTES = 47104u * 4u;

__global__ __launch_bounds__(256, 1)
void flash_mma(const float* __restrict__ Qf, const float* __restrict__ Kf,
               const float* __restrict__ Vf, float* __restrict__ Out) {
    extern __shared__ float sm[];
    const uint32_t sb = smem_u32(sm);

    const int t    = threadIdx.x;
    const int wid  = t >> 5;
    const int lane = t & 31;
    const int g    = lane >> 2;
    const int tig  = lane & 3;
    const int wr   = wid >> 1;
    const int wc   = wid & 1;
    const int bh   = blockIdx.x;
    const int qt   = (int)gridDim.y - 1 - (int)blockIdx.y;
    const int q0   = qt * 64;
    const int b    = bh >> 4, h = bh & 15;

    const float* Kbase = Kf + (size_t)bh * S_ * QD_;
    const float* Vbase = Vf + (size_t)bh * S_ * VD_;

#define KV_LOAD(bufK, bufV, jj)                                                 \
    do {                                                                        \
        const float* Kb_ = Kbase + (size_t)(jj) * 64 * QD_;                     \
        const float* Vb_ = Vbase + (size_t)(jj) * 64 * VD_;                     \
        _Pragma("unroll")                                                       \
        for (int i_ = 0; i_ < 12; i_++) {                                       \
            const int f_ = t + i_ * 256;                                        \
            const int r_ = f_ / 48, c_ = (f_ % 48) * 4;                         \
            CPA16(sb + (uint32_t)((bufK) + r_ * 196 + c_) * 4u,                 \
                  Kb_ + r_ * QD_ + c_, 16);                                     \
        }                                                                       \
        _Pragma("unroll")                                                       \
        for (int i_ = 0; i_ < 8; i_++) {                                        \
            const int f_ = t + i_ * 256;                                        \
            const int r_ = f_ >> 5, c_ = (f_ & 31) * 4;                         \
            CPA16(sb + (uint32_t)((bufV) + r_ * 136 + c_) * 4u,                 \
                  Vb_ + r_ * VD_ + c_, 16);                                     \
        }                                                                       \
        asm volatile("cp.async.commit_group;" ::: "memory");                    \
    } while (0)

    {
        const float* Qb = Qf + ((size_t)bh * S_ + q0) * QD_;
#pragma unroll
        for (int i = 0; i < 12; i++) {
            const int f = t + i * 256;
            const int r = f / 48, c = (f % 48) * 4;
            CPA16(sb + (uint32_t)(FK1 + r * 196 + c) * 4u, Qb + r * QD_ + c, 16);
        }
        asm volatile("cp.async.commit_group;" ::: "memory");
    }
    KV_LOAD(FK0, FV0, 0);
    asm volatile("cp.async.wait_group 1;" ::: "memory");
    __syncthreads();

    uint32_t qr[24][4];
    {
        const float* Qs = sm + FK1 + (wr * 16 + g) * 196 + tig;
#pragma unroll
        for (int ks = 0; ks < 24; ks++) {
            qr[ks][0] = __float_as_uint(Qs[ks * 8]);
            qr[ks][1] = __float_as_uint(Qs[ks * 8 + 8 * 196]);
            qr[ks][2] = __float_as_uint(Qs[ks * 8 + 4]);
            qr[ks][3] = __float_as_uint(Qs[ks * 8 + 8 * 196 + 4]);
        }
    }
    __syncthreads();
    if (qt >= 1) KV_LOAD(FK1, FV1, 1);

    float mi0 = -INFINITY, mi1 = -INFINITY, li0 = 0.f, li1 = 0.f;
    float acc[8][4];
#pragma unroll
    for (int nt = 0; nt < 8; nt++)
#pragma unroll
        for (int c = 0; c < 4; c++) acc[nt][c] = 0.f;

    const int row0 = wr * 16 + g;
    const int row1 = row0 + 8;

    for (int j = 0; j <= qt; ++j) {
        if (j < qt) asm volatile("cp.async.wait_group 1;" ::: "memory");
        else        asm volatile("cp.async.wait_group 0;" ::: "memory");
        __syncthreads();

        const int KB = (j & 1) ? FK1 : FK0;
        const int VB = (j & 1) ? FV1 : FV0;

        float s4[4][4];
#pragma unroll
        for (int nt = 0; nt < 4; nt++)
#pragma unroll
            for (int c = 0; c < 4; c++) s4[nt][c] = 0.f;

#pragma unroll
        for (int ks = 0; ks < 24; ks++) {
            uint32_t bf[4][2];
#pragma unroll
            for (int nt = 0; nt < 4; nt++) {
                const float* kp = sm + KB + (wc * 32 + nt * 8 + g) * 196 + ks * 8 + tig;
                bf[nt][0] = __float_as_uint(kp[0]);
                bf[nt][1] = __float_as_uint(kp[4]);
            }
#pragma unroll
            for (int nt = 0; nt < 4; nt++)
                MMA_TF32(s4[nt], qr[ks], bf[nt]);
        }

        if (j == qt) {
#pragma unroll
            for (int nt = 0; nt < 4; nt++) {
                const int col = wc * 32 + nt * 8 + tig * 2;
                if (col     > row0) s4[nt][0] = -1e30f;
                if (col + 1 > row0) s4[nt][1] = -1e30f;
                if (col     > row1) s4[nt][2] = -1e30f;
                if (col + 1 > row1) s4[nt][3] = -1e30f;
            }
        }

        float pm0 = fmaxf(fmaxf(s4[0][0], s4[0][1]), fmaxf(s4[1][0], s4[1][1]));
        pm0 = fmaxf(pm0, fmaxf(fmaxf(s4[2][0], s4[2][1]), fmaxf(s4[3][0], s4[3][1])));
        float pm1 = fmaxf(fmaxf(s4[0][2], s4[0][3]), fmaxf(s4[1][2], s4[1][3]));
        pm1 = fmaxf(pm1, fmaxf(fmaxf(s4[2][2], s4[2][3]), fmaxf(s4[3][2], s4[3][3])));
        pm0 = fmaxf(pm0, __shfl_xor_sync(0xffffffffu, pm0, 1));
        pm0 = fmaxf(pm0, __shfl_xor_sync(0xffffffffu, pm0, 2));
        pm1 = fmaxf(pm1, __shfl_xor_sync(0xffffffffu, pm1, 1));
        pm1 = fmaxf(pm1, __shfl_xor_sync(0xffffffffu, pm1, 2));
        if (tig == 0) {
            sm[FRM + wc * 64 + row0] = pm0;
            sm[FRM + wc * 64 + row1] = pm1;
        }
        __syncthreads();
        const float rm0 = fmaxf(sm[FRM + row0], sm[FRM + 64 + row0]);
        const float rm1 = fmaxf(sm[FRM + row1], sm[FRM + 64 + row1]);
        const float mn0 = fmaxf(mi0, rm0), mn1 = fmaxf(mi1, rm1);
        const float corr0 = __expf(mi0 - mn0), corr1 = __expf(mi1 - mn1);
        mi0 = mn0; mi1 = mn1;

        float rs0 = 0.f, rs1 = 0.f;
#pragma unroll
        for (int nt = 0; nt < 4; nt++) {
            s4[nt][0] = __expf(s4[nt][0] - mn0); rs0 += s4[nt][0];
            s4[nt][1] = __expf(s4[nt][1] - mn0); rs0 += s4[nt][1];
            s4[nt][2] = __expf(s4[nt][2] - mn1); rs1 += s4[nt][2];
            s4[nt][3] = __expf(s4[nt][3] - mn1); rs1 += s4[nt][3];
        }
        rs0 += __shfl_xor_sync(0xffffffffu, rs0, 1);
        rs0 += __shfl_xor_sync(0xffffffffu, rs0, 2);
        rs1 += __shfl_xor_sync(0xffffffffu, rs1, 1);
        rs1 += __shfl_xor_sync(0xffffffffu, rs1, 2);
        if (tig == 0) {
            sm[FRS + wc * 64 + row0] = rs0;
            sm[FRS + wc * 64 + row1] = rs1;
        }
#pragma unroll
        for (int nt = 0; nt < 4; nt++) {
            const int col = wc * 32 + nt * 8 + tig * 2;
            *(float2*)&sm[FPS + row0 * 68 + col] =
                make_float2(to_tf32(s4[nt][0]), to_tf32(s4[nt][1]));
            *(float2*)&sm[FPS + row1 * 68 + col] =
                make_float2(to_tf32(s4[nt][2]), to_tf32(s4[nt][3]));
        }
        __syncthreads();

        li0 = li0 * corr0 + sm[FRS + row0] + sm[FRS + 64 + row0];
        li1 = li1 * corr1 + sm[FRS + row1] + sm[FRS + 64 + row1];
#pragma unroll
        for (int nt = 0; nt < 8; nt++) {
            acc[nt][0] *= corr0; acc[nt][1] *= corr0;
            acc[nt][2] *= corr1; acc[nt][3] *= corr1;
        }

#pragma unroll
        for (int ks = 0; ks < 8; ks++) {
            uint32_t a[4];
            const float* pp = sm + FPS + row0 * 68 + ks * 8 + tig;
            a[0] = __float_as_uint(pp[0]);
            a[1] = __float_as_uint(pp[8 * 68]);
            a[2] = __float_as_uint(pp[4]);
            a[3] = __float_as_uint(pp[8 * 68 + 4]);
#pragma unroll
            for (int nt = 0; nt < 8; nt++) {
                uint32_t bf[2];
                const float* vp = sm + VB + (ks * 8 + tig) * 136 + wc * 64 + nt * 8 + g;
                bf[0] = __float_as_uint(vp[0]);
                bf[1] = __float_as_uint(vp[4 * 136]);
                MMA_TF32(acc[nt], a, bf);
            }
        }
        __syncthreads();

        if (j + 2 <= qt) {
            if (j & 1) KV_LOAD(FK1, FV1, j + 2);
            else       KV_LOAD(FK0, FV0, j + 2);
        }
    }
#undef KV_LOAD

    const float linv0 = 1.0f / li0;
    const float linv1 = 1.0f / li1;
    const size_t r0g = (size_t)(b * S_ + q0 + row0) * (H_ * VD_) + h * VD_;
    const size_t r1g = (size_t)(b * S_ + q0 + row1) * (H_ * VD_) + h * VD_;
#pragma unroll
    for (int nt = 0; nt < 8; nt++) {
        const int col = wc * 64 + nt * 8 + tig * 2;
        *(float2*)&Out[r0g + col] =
            make_float2(to_tf32(acc[nt][0] * linv0), to_tf32(acc[nt][1] * linv0));
        *(float2*)&Out[r1g + col] =
            make_float2(to_tf32(acc[nt][2] * linv1), to_tf32(acc[nt][3] * linv1));
    }
}

// ---------------------------------------------------------------------------
// Launch: fork-join stream overlap of {q-projection} with {ckv chain}
// ---------------------------------------------------------------------------
extern "C" void kernel_launch(void* const* d_in, const int* in_sizes, int n_in,
                              void* d_out, int out_size) {
    const float* x      = (const float*)d_in[0];
    const float* rope   = (const float*)d_in[1];
    const float* wq     = (const float*)d_in[2];
    const float* wkva   = (const float*)d_in[3];
    const float* norm_w = (const float*)d_in[4];
    const float* wkvb   = (const float*)d_in[5];
    const float* wo     = (const float*)d_in[6];
    float* out = (float*)d_out;

    float *p_qckv, *p_norm, *p_kv, *p_qf, *p_kf, *p_v, *p_attn;
    float *p_xr, *p_wqkva, *p_wkvbr, *p_wor;
    cudaGetSymbolAddress((void**)&p_qckv,  g_qckv);
    cudaGetSymbolAddress((void**)&p_norm,  g_norm);
    cudaGetSymbolAddress((void**)&p_kv,    g_kv);
    cudaGetSymbolAddress((void**)&p_qf,    g_qf);
    cudaGetSymbolAddress((void**)&p_kf,    g_kf);
    cudaGetSymbolAddress((void**)&p_v,     g_v);
    cudaGetSymbolAddress((void**)&p_attn,  g_attn);
    cudaGetSymbolAddress((void**)&p_xr,    g_xr);
    cudaGetSymbolAddress((void**)&p_wqkva, g_wqkva);
    cudaGetSymbolAddress((void**)&p_wkvbr, g_wkvbr);
    cudaGetSymbolAddress((void**)&p_wor,   g_wor);

    cudaFuncSetAttribute(mma_gemm, cudaFuncAttributeMaxDynamicSharedMemorySize,
                         MG_SMEM_BYTES);
    cudaFuncSetAttribute(flash_mma, cudaFuncAttributeMaxDynamicSharedMemorySize,
                         FL_SMEM_BYTES);

    // Side stream + events, created once (host-side objects only).
    static cudaStream_t s1 = nullptr;
    static cudaEvent_t  e0 = nullptr, e1 = nullptr;
    if (s1 == nullptr) {
        cudaStreamCreateWithFlags(&s1, cudaStreamNonBlocking);
        cudaEventCreateWithFlags(&e0, cudaEventDisableTiming);
        cudaEventCreateWithFlags(&e1, cudaEventDisableTiming);
    }

    // 0) round x (needed by both branches)
    round_tf32_kernel<<<1024, 256>>>((const float4*)x, (float4*)p_xr,
                                     BS_ * DIM_ / 4);

    // ---- fork ----
    cudaEventRecord(e0, 0);
    cudaStreamWaitEvent(s1, e0, 0);

    // Branch s1: round wq, then q-projection tiles (cols 0..3071)
    round_tf32_kernel<<<1024, 256, 0, s1>>>((const float4*)wq, (float4*)p_wqkva,
                                            H_ * QD_ * DIM_ / 4);
    mma_gemm<<<dim3(12, 32), 256, MG_SMEM_BYTES, s1>>>(p_xr, p_wqkva, p_qckv,
                                                       NQC_, DIM_, 0);
    cudaEventRecord(e1, s1);

    // Main stream: round remaining weights, ckv tiles, rmsnorm, kv GEMM
    round3_kernel<<<1024, 256>>>(
        (const float4*)wkva, (float4*)(p_wqkva + (size_t)H_ * QD_ * DIM_),
        (KV_LORA_ + ROPE_) * DIM_ / 4,
        (const float4*)wkvb, (float4*)p_wkvbr, H_ * 256 * KV_LORA_ / 4,
        (const float4*)wo,   (float4*)p_wor,   DIM_ * H_ * VD_ / 4);
    // ckv tiles of qckv (cols 3072..3647) -> rmsnorm inputs
    mma_gemm<<<dim3(3, 32), 256, MG_SMEM_BYTES>>>(p_xr, p_wqkva, p_qckv,
                                                  NQC_, DIM_, 12);
    rmsnorm_kernel<<<BS_, 128>>>(p_qckv, norm_w, p_norm);
    mma_gemm<<<dim3(16, 32), 256, MG_SMEM_BYTES>>>(p_norm, p_wkvbr, p_kv,
                                                   H_ * 256, KV_LORA_, 0);

    // ---- join ----
    cudaStreamWaitEvent(0, e1, 0);

    // assemble, flash, out-projection
    assemble_kernel<<<BS_, 256>>>(p_qckv, p_kv, rope, p_qf, p_kf, p_v);
    flash_mma<<<dim3(B_ * H_, S_ / 64), 256, FL_SMEM_BYTES>>>(p_qf, p_kf, p_v, p_attn);
    mma_gemm<<<dim3(8, 32), 256, MG_SMEM_BYTES>>>(p_attn, p_wor, out,
                                                  DIM_, DIM_, 0);
}

// round 17
// speedup vs baseline: 2.2048x; 1.0123x over previous
#include <cuda_runtime.h>
#include <cuda_bf16.h>
#include <math.h>
#include <stdint.h>

// Problem constants
#define B_       2
#define S_       2048
#define DIM_     2048
#define H_       16
#define KV_LORA_ 512
#define NOPE_    128
#define ROPE_    64
#define VD_      128
#define QD_      192
#define BS_      (B_ * S_)    // 4096
#define NQC_     3648         // fused q (3072) + ckv (576) output width

// ---------------------------------------------------------------------------
// Scratch
// ---------------------------------------------------------------------------
__device__ float g_qckv[BS_ * NQC_];
__device__ float g_norm[BS_ * KV_LORA_];
__device__ float g_kv  [BS_ * H_ * (NOPE_ + VD_)];
__device__ float g_qf  [B_ * H_ * S_ * QD_];
__device__ float g_kf  [B_ * H_ * S_ * QD_];
__device__ float g_v   [B_ * H_ * S_ * VD_];
__device__ float g_attn[BS_ * H_ * VD_];

__device__ float g_xr   [BS_ * DIM_];
__device__ float g_wqkva[NQC_ * DIM_];
__device__ float g_wkvbr[H_ * 256 * KV_LORA_];
__device__ float g_wor  [DIM_ * H_ * VD_];

// ---------------------------------------------------------------------------
// Helpers
// ---------------------------------------------------------------------------
__device__ __forceinline__ float to_tf32(float x) {
    uint32_t u;
    asm("cvt.rna.tf32.f32 %0, %1;" : "=r"(u) : "f"(x));
    return __uint_as_float(u);
}
__device__ __forceinline__ uint32_t smem_u32(const void* p) {
    uint32_t a;
    asm("{ .reg .u64 t; cvta.to.shared.u64 t, %1; cvt.u32.u64 %0, t; }"
        : "=r"(a) : "l"(p));
    return a;
}
#define CPA16(dst, src, sz) \
    asm volatile("cp.async.cg.shared.global [%0], [%1], 16, %2;" \
                 :: "r"(dst), "l"(src), "r"(sz) : "memory")
#define MMA_TF32(d, a, b)                                                     \
    asm volatile(                                                             \
        "mma.sync.aligned.m16n8k8.row.col.f32.tf32.tf32.f32 "                 \
        "{%0,%1,%2,%3}, {%4,%5,%6,%7}, {%8,%9}, {%0,%1,%2,%3};"               \
        : "+f"((d)[0]), "+f"((d)[1]), "+f"((d)[2]), "+f"((d)[3])              \
        : "r"((a)[0]), "r"((a)[1]), "r"((a)[2]), "r"((a)[3]),                 \
          "r"((b)[0]), "r"((b)[1]))

// ---------------------------------------------------------------------------
// tf32 mma.sync GEMM (R12-proven mainloop): C[M,N] = A[M,K] @ B[N,K]^T
// CTA 128x256, BK=32, 256 threads = 8 warps, warp tile 64x64, 3-stage.
// n_off shifts the N-tile origin; (m_base, m_hop) map blockIdx.y to row
// tiles:  m_tile = m_base + by + (by>>3)*m_hop   (m_hop=0 -> identity).
// ---------------------------------------------------------------------------
constexpr int MG_STR    = 36;
constexpr int MG_ABUF   = 128 * MG_STR;
constexpr int MG_BBUF   = 256 * MG_STR;
constexpr int MG_STAGE  = MG_ABUF + MG_BBUF;       // 13824 floats
constexpr unsigned MG_SMEM_BYTES = 3u * MG_STAGE * sizeof(float);  // 165888

__global__ __launch_bounds__(256, 1)
void mma_gemm(const float* __restrict__ A, const float* __restrict__ Bm,
              float* __restrict__ C, int N, int K, int n_off,
              int m_base, int m_hop) {
    extern __shared__ float sm[];
    const uint32_t sb = smem_u32(sm);

    const int t    = threadIdx.x;
    const int wid  = t >> 5;
    const int lane = t & 31;
    const int g    = lane >> 2;
    const int tig  = lane & 3;
    const int wm   = (wid & 1) * 64;
    const int wn   = (wid >> 1) * 64;
    const int by   = (int)blockIdx.y;
    const int m0   = (m_base + by + ((by >> 3) * m_hop)) * 128;
    const int n0   = (blockIdx.x + n_off) * 256;
    const int NK   = K / 32;

    int arow[4], ac4[4];
    const float* Asrc[4];
#pragma unroll
    for (int j = 0; j < 4; j++) {
        const int f = t + j * 256;
        arow[j] = f >> 3;
        ac4[j]  = f & 7;
        Asrc[j] = A + (size_t)(m0 + arow[j]) * K + ac4[j] * 4;
    }
    int brow[8], bc4[8], bsz[8];
    const float* Bsrc[8];
#pragma unroll
    for (int j = 0; j < 8; j++) {
        const int f = t + j * 256;
        brow[j] = f >> 3;
        bc4[j]  = f & 7;
        const int gr = n0 + brow[j];
        bsz[j]  = (gr < N) ? 16 : 0;
        Bsrc[j] = Bm + (size_t)((gr < N) ? gr : 0) * K + bc4[j] * 4;
    }

#define MG_LOAD(stg, kc)                                                        \
    do {                                                                        \
        const int k0_ = (kc) * 32;                                              \
        const uint32_t sA_ = sb + (uint32_t)((stg) * MG_STAGE) * 4u;            \
        const uint32_t sB_ = sA_ + (uint32_t)MG_ABUF * 4u;                      \
        _Pragma("unroll")                                                       \
        for (int j = 0; j < 4; j++)                                             \
            CPA16(sA_ + (uint32_t)(arow[j] * MG_STR + ac4[j] * 4) * 4u,         \
                  Asrc[j] + k0_, 16);                                           \
        _Pragma("unroll")                                                       \
        for (int j = 0; j < 8; j++)                                             \
            CPA16(sB_ + (uint32_t)(brow[j] * MG_STR + bc4[j] * 4) * 4u,         \
                  Bsrc[j] + k0_, bsz[j]);                                       \
    } while (0)

    float acc[4][8][4];
#pragma unroll
    for (int mi = 0; mi < 4; mi++)
#pragma unroll
        for (int ni = 0; ni < 8; ni++)
#pragma unroll
            for (int c = 0; c < 4; c++) acc[mi][ni][c] = 0.0f;

    MG_LOAD(0, 0);
    asm volatile("cp.async.commit_group;" ::: "memory");
    MG_LOAD(1, 1);
    asm volatile("cp.async.commit_group;" ::: "memory");

    int stg = 0;
    for (int i = 0; i < NK; ++i) {
        asm volatile("cp.async.wait_group 1;" ::: "memory");
        __syncthreads();

        const float* Ab = sm + stg * MG_STAGE;
        const float* Bb = Ab + MG_ABUF;
#pragma unroll
        for (int ks = 0; ks < 4; ks++) {
            const int k0 = ks * 8;
            uint32_t a[4][4], b[8][2];
#pragma unroll
            for (int mi = 0; mi < 4; mi++) {
                const float* ap = Ab + (wm + mi * 16 + g) * MG_STR + k0 + tig;
                a[mi][0] = __float_as_uint(ap[0]);
                a[mi][1] = __float_as_uint(ap[8 * MG_STR]);
                a[mi][2] = __float_as_uint(ap[4]);
                a[mi][3] = __float_as_uint(ap[8 * MG_STR + 4]);
            }
#pragma unroll
            for (int ni = 0; ni < 8; ni++) {
                const float* bp = Bb + (wn + ni * 8 + g) * MG_STR + k0 + tig;
                b[ni][0] = __float_as_uint(bp[0]);
                b[ni][1] = __float_as_uint(bp[4]);
            }
#pragma unroll
            for (int mi = 0; mi < 4; mi++)
#pragma unroll
                for (int ni = 0; ni < 8; ni++)
                    MMA_TF32(acc[mi][ni], a[mi], b[ni]);
        }

        if (i + 2 < NK) MG_LOAD((stg + 2) % 3, i + 2);
        asm volatile("cp.async.commit_group;" ::: "memory");
        stg = (stg + 1) % 3;
    }
#undef MG_LOAD

#pragma unroll
    for (int mi = 0; mi < 4; mi++) {
        const int rr = m0 + wm + mi * 16 + g;
#pragma unroll
        for (int ni = 0; ni < 8; ni++) {
            const int cc = n0 + wn + ni * 8 + tig * 2;
            if (cc < N) {
                float2 v0 = make_float2(acc[mi][ni][0], acc[mi][ni][1]);
                float2 v1 = make_float2(acc[mi][ni][2], acc[mi][ni][3]);
                *(float2*)&C[(size_t)rr * N + cc]       = v0;
                *(float2*)&C[(size_t)(rr + 8) * N + cc] = v1;
            }
        }
    }
}

// ---------------------------------------------------------------------------
// tf32 rounding passes
// ---------------------------------------------------------------------------
__global__ __launch_bounds__(256) void round_tf32_kernel(const float4* __restrict__ src,
                                                         float4* __restrict__ dst, int n4) {
    for (int i = blockIdx.x * 256 + threadIdx.x; i < n4; i += gridDim.x * 256) {
        float4 v = src[i];
        v.x = to_tf32(v.x); v.y = to_tf32(v.y);
        v.z = to_tf32(v.z); v.w = to_tf32(v.w);
        dst[i] = v;
    }
}

__global__ __launch_bounds__(256) void round3_kernel(
    const float4* __restrict__ s1, float4* __restrict__ d1, int n1,
    const float4* __restrict__ s2, float4* __restrict__ d2, int n2,
    const float4* __restrict__ s3, float4* __restrict__ d3, int n3) {
    const int total = n1 + n2 + n3;
    for (int i = blockIdx.x * 256 + threadIdx.x; i < total; i += gridDim.x * 256) {
        const float4* sp;
        float4* dp;
        int k;
        if (i < n1)            { sp = s1; dp = d1; k = i; }
        else if (i < n1 + n2)  { sp = s2; dp = d2; k = i - n1; }
        else                   { sp = s3; dp = d3; k = i - n1 - n2; }
        float4 v = sp[k];
        v.x = to_tf32(v.x); v.y = to_tf32(v.y);
        v.z = to_tf32(v.z); v.w = to_tf32(v.w);
        dp[k] = v;
    }
}

// ---------------------------------------------------------------------------
// RMSNorm over qckv[row, 3072:3584]; tf32-rounded out
// ---------------------------------------------------------------------------
__global__ __launch_bounds__(128) void rmsnorm_kernel(const float* __restrict__ qckv,
                                                      const float* __restrict__ w,
                                                      float* __restrict__ outp) {
    const int row = blockIdx.x;
    const int t   = threadIdx.x;
    const float* xr = qckv + (size_t)row * NQC_ + H_ * QD_;
    float v[4];
    float s = 0.f;
#pragma unroll
    for (int i = 0; i < 4; i++) { v[i] = xr[t + i * 128]; s += v[i] * v[i]; }
#pragma unroll
    for (int m = 16; m >= 1; m >>= 1) s += __shfl_xor_sync(0xffffffffu, s, m);
    __shared__ float ws[4];
    if ((t & 31) == 0) ws[t >> 5] = s;
    __syncthreads();
    s = ws[0] + ws[1] + ws[2] + ws[3];
    const float inv = rsqrtf(s * (1.0f / (float)KV_LORA_) + 1e-6f);
    float* orow = outp + (size_t)row * KV_LORA_;
#pragma unroll
    for (int i = 0; i < 4; i++) orow[t + i * 128] = to_tf32(v[i] * inv * w[t + i * 128]);
}

// ---------------------------------------------------------------------------
// RoPE + assembly from fused qckv; outputs tf32-rounded
// ---------------------------------------------------------------------------
__global__ __launch_bounds__(256) void assemble_kernel(const float* __restrict__ qckv,
                                                       const float* __restrict__ kv,
                                                       const float* __restrict__ rope,
                                                       float* __restrict__ qf,
                                                       float* __restrict__ kf,
                                                       float* __restrict__ v) {
    const int row = blockIdx.x;
    const int s   = row & (S_ - 1);
    const int b   = row >> 11;
    const int t   = threadIdx.x;

    __shared__ float cs[64], sn[64], kr[64];
    if (t < 64) {
        cs[t] = rope[(size_t)s * 128 + t];
        sn[t] = rope[(size_t)s * 128 + 64 + t];
    }
    __syncthreads();
    if (t < 64) {
        const float* cr = qckv + (size_t)row * NQC_ + H_ * QD_ + KV_LORA_;
        float k0  = cr[t];
        float rot = (t < 32) ? -cr[t + 32] : cr[t - 32];
        kr[t] = k0 * cs[t] + rot * sn[t];
    }
    __syncthreads();

    const float scale = rsqrtf((float)QD_);
    for (int idx = t; idx < H_ * QD_; idx += 256) {
        const int h = idx / QD_;
        const int d = idx - h * QD_;
        const size_t dst = ((size_t)(b * H_ + h) * S_ + s) * QD_ + d;
        const float* qrow = qckv + (size_t)row * NQC_ + h * QD_;
        float qv;
        if (d < NOPE_) {
            qv = qrow[d];
        } else {
            const int r   = d - NOPE_;
            float q1  = qrow[NOPE_ + r];
            float rot = (r < 32) ? -qrow[NOPE_ + r + 32] : qrow[NOPE_ + r - 32];
            qv = q1 * cs[r] + rot * sn[r];
        }
        qf[dst] = to_tf32(qv * scale);
        float kvv;
        if (d < NOPE_) kvv = kv[(size_t)row * (H_ * 256) + h * 256 + d];
        else           kvv = kr[d - NOPE_];
        kf[dst] = to_tf32(kvv);
    }
    for (int idx = t; idx < H_ * VD_; idx += 256) {
        const int h  = idx >> 7;
        const int dv = idx & 127;
        v[((size_t)(b * H_ + h) * S_ + s) * VD_ + dv] =
            to_tf32(kv[(size_t)row * (H_ * 256) + h * 256 + NOPE_ + dv]);
    }
}

// ---------------------------------------------------------------------------
// Tensor-core causal flash attention (tf32 mma.sync); qt_off splits the
// q-tile range across launches:  qt = qt_off + (gridDim.y - 1 - blockIdx.y).
// ---------------------------------------------------------------------------
constexpr int FK0 = 0;
constexpr int FV0 = 12544;
constexpr int FK1 = 21248;
constexpr int FV1 = 33792;
constexpr int FPS = 42496;
constexpr int FRM = 46848;
constexpr int FRS = 46976;
constexpr unsigned FL_SMEM_BYTES = 47104u * 4u;

__global__ __launch_bounds__(256, 1)
void flash_mma(const float* __restrict__ Qf, const float* __restrict__ Kf,
               const float* __restrict__ Vf, float* __restrict__ Out, int qt_off) {
    extern __shared__ float sm[];
    const uint32_t sb = smem_u32(sm);

    const int t    = threadIdx.x;
    const int wid  = t >> 5;
    const int lane = t & 31;
    const int g    = lane >> 2;
    const int tig  = lane & 3;
    const int wr   = wid >> 1;
    const int wc   = wid & 1;
    const int bh   = blockIdx.x;
    const int qt   = qt_off + (int)gridDim.y - 1 - (int)blockIdx.y;
    const int q0   = qt * 64;
    const int b    = bh >> 4, h = bh & 15;

    const float* Kbase = Kf + (size_t)bh * S_ * QD_;
    const float* Vbase = Vf + (size_t)bh * S_ * VD_;

#define KV_LOAD(bufK, bufV, jj)                                                 \
    do {                                                                        \
        const float* Kb_ = Kbase + (size_t)(jj) * 64 * QD_;                     \
        const float* Vb_ = Vbase + (size_t)(jj) * 64 * VD_;                     \
        _Pragma("unroll")                                                       \
        for (int i_ = 0; i_ < 12; i_++) {                                       \
            const int f_ = t + i_ * 256;                                        \
            const int r_ = f_ / 48, c_ = (f_ % 48) * 4;                         \
            CPA16(sb + (uint32_t)((bufK) + r_ * 196 + c_) * 4u,                 \
                  Kb_ + r_ * QD_ + c_, 16);                                     \
        }                                                                       \
        _Pragma("unroll")                                                       \
        for (int i_ = 0; i_ < 8; i_++) {                                        \
            const int f_ = t + i_ * 256;                                        \
            const int r_ = f_ >> 5, c_ = (f_ & 31) * 4;                         \
            CPA16(sb + (uint32_t)((bufV) + r_ * 136 + c_) * 4u,                 \
                  Vb_ + r_ * VD_ + c_, 16);                                     \
        }                                                                       \
        asm volatile("cp.async.commit_group;" ::: "memory");                    \
    } while (0)

    {
        const float* Qb = Qf + ((size_t)bh * S_ + q0) * QD_;
#pragma unroll
        for (int i = 0; i < 12; i++) {
            const int f = t + i * 256;
            const int r = f / 48, c = (f % 48) * 4;
            CPA16(sb + (uint32_t)(FK1 + r * 196 + c) * 4u, Qb + r * QD_ + c, 16);
        }
        asm volatile("cp.async.commit_group;" ::: "memory");
    }
    KV_LOAD(FK0, FV0, 0);
    asm volatile("cp.async.wait_group 1;" ::: "memory");
    __syncthreads();

    uint32_t qr[24][4];
    {
        const float* Qs = sm + FK1 + (wr * 16 + g) * 196 + tig;
#pragma unroll
        for (int ks = 0; ks < 24; ks++) {
            qr[ks][0] = __float_as_uint(Qs[ks * 8]);
            qr[ks][1] = __float_as_uint(Qs[ks * 8 + 8 * 196]);
            qr[ks][2] = __float_as_uint(Qs[ks * 8 + 4]);
            qr[ks][3] = __float_as_uint(Qs[ks * 8 + 8 * 196 + 4]);
        }
    }
    __syncthreads();
    if (qt >= 1) KV_LOAD(FK1, FV1, 1);

    float mi0 = -INFINITY, mi1 = -INFINITY, li0 = 0.f, li1 = 0.f;
    float acc[8][4];
#pragma unroll
    for (int nt = 0; nt < 8; nt++)
#pragma unroll
        for (int c = 0; c < 4; c++) acc[nt][c] = 0.f;

    const int row0 = wr * 16 + g;
    const int row1 = row0 + 8;

    for (int j = 0; j <= qt; ++j) {
        if (j < qt) asm volatile("cp.async.wait_group 1;" ::: "memory");
        else        asm volatile("cp.async.wait_group 0;" ::: "memory");
        __syncthreads();

        const int KB = (j & 1) ? FK1 : FK0;
        const int VB = (j & 1) ? FV1 : FV0;

        float s4[4][4];
#pragma unroll
        for (int nt = 0; nt < 4; nt++)
#pragma unroll
            for (int c = 0; c < 4; c++) s4[nt][c] = 0.f;

#pragma unroll
        for (int ks = 0; ks < 24; ks++) {
            uint32_t bf[4][2];
#pragma unroll
            for (int nt = 0; nt < 4; nt++) {
                const float* kp = sm + KB + (wc * 32 + nt * 8 + g) * 196 + ks * 8 + tig;
                bf[nt][0] = __float_as_uint(kp[0]);
                bf[nt][1] = __float_as_uint(kp[4]);
            }
#pragma unroll
            for (int nt = 0; nt < 4; nt++)
                MMA_TF32(s4[nt], qr[ks], bf[nt]);
        }

        if (j == qt) {
#pragma unroll
            for (int nt = 0; nt < 4; nt++) {
                const int col = wc * 32 + nt * 8 + tig * 2;
                if (col     > row0) s4[nt][0] = -1e30f;
                if (col + 1 > row0) s4[nt][1] = -1e30f;
                if (col     > row1) s4[nt][2] = -1e30f;
                if (col + 1 > row1) s4[nt][3] = -1e30f;
            }
        }

        float pm0 = fmaxf(fmaxf(s4[0][0], s4[0][1]), fmaxf(s4[1][0], s4[1][1]));
        pm0 = fmaxf(pm0, fmaxf(fmaxf(s4[2][0], s4[2][1]), fmaxf(s4[3][0], s4[3][1])));
        float pm1 = fmaxf(fmaxf(s4[0][2], s4[0][3]), fmaxf(s4[1][2], s4[1][3]));
        pm1 = fmaxf(pm1, fmaxf(fmaxf(s4[2][2], s4[2][3]), fmaxf(s4[3][2], s4[3][3])));
        pm0 = fmaxf(pm0, __shfl_xor_sync(0xffffffffu, pm0, 1));
        pm0 = fmaxf(pm0, __shfl_xor_sync(0xffffffffu, pm0, 2));
        pm1 = fmaxf(pm1, __shfl_xor_sync(0xffffffffu, pm1, 1));
        pm1 = fmaxf(pm1, __shfl_xor_sync(0xffffffffu, pm1, 2));
        if (tig == 0) {
            sm[FRM + wc * 64 + row0] = pm0;
            sm[FRM + wc * 64 + row1] = pm1;
        }
        __syncthreads();
        const float rm0 = fmaxf(sm[FRM + row0], sm[FRM + 64 + row0]);
        const float rm1 = fmaxf(sm[FRM + row1], sm[FRM + 64 + row1]);
        const float mn0 = fmaxf(mi0, rm0), mn1 = fmaxf(mi1, rm1);
        const float corr0 = __expf(mi0 - mn0), corr1 = __expf(mi1 - mn1);
        mi0 = mn0; mi1 = mn1;

        float rs0 = 0.f, rs1 = 0.f;
#pragma unroll
        for (int nt = 0; nt < 4; nt++) {
            s4[nt][0] = __expf(s4[nt][0] - mn0); rs0 += s4[nt][0];
            s4[nt][1] = __expf(s4[nt][1] - mn0); rs0 += s4[nt][1];
            s4[nt][2] = __expf(s4[nt][2] - mn1); rs1 += s4[nt][2];
            s4[nt][3] = __expf(s4[nt][3] - mn1); rs1 += s4[nt][3];
        }
        rs0 += __shfl_xor_sync(0xffffffffu, rs0, 1);
        rs0 += __shfl_xor_sync(0xffffffffu, rs0, 2);
        rs1 += __shfl_xor_sync(0xffffffffu, rs1, 1);
        rs1 += __shfl_xor_sync(0xffffffffu, rs1, 2);
        if (tig == 0) {
            sm[FRS + wc * 64 + row0] = rs0;
            sm[FRS + wc * 64 + row1] = rs1;
        }
#pragma unroll
        for (int nt = 0; nt < 4; nt++) {
            const int col = wc * 32 + nt * 8 + tig * 2;
            *(float2*)&sm[FPS + row0 * 68 + col] =
                make_float2(to_tf32(s4[nt][0]), to_tf32(s4[nt][1]));
            *(float2*)&sm[FPS + row1 * 68 + col] =
                make_float2(to_tf32(s4[nt][2]), to_tf32(s4[nt][3]));
        }
        __syncthreads();

        li0 = li0 * corr0 + sm[FRS + row0] + sm[FRS + 64 + row0];
        li1 = li1 * corr1 + sm[FRS + row1] + sm[FRS + 64 + row1];
#pragma unroll
        for (int nt = 0; nt < 8; nt++) {
            acc[nt][0] *= corr0; acc[nt][1] *= corr0;
            acc[nt][2] *= corr1; acc[nt][3] *= corr1;
        }

#pragma unroll
        for (int ks = 0; ks < 8; ks++) {
            uint32_t a[4];
            const float* pp = sm + FPS + row0 * 68 + ks * 8 + tig;
            a[0] = __float_as_uint(pp[0]);
            a[1] = __float_as_uint(pp[8 * 68]);
            a[2] = __float_as_uint(pp[4]);
            a[3] = __float_as_uint(pp[8 * 68 + 4]);
#pragma unroll
            for (int nt = 0; nt < 8; nt++) {
                uint32_t bf[2];
                const float* vp = sm + VB + (ks * 8 + tig) * 136 + wc * 64 + nt * 8 + g;
                bf[0] = __float_as_uint(vp[0]);
                bf[1] = __float_as_uint(vp[4 * 136]);
                MMA_TF32(acc[nt], a, bf);
            }
        }
        __syncthreads();

        if (j + 2 <= qt) {
            if (j & 1) KV_LOAD(FK1, FV1, j + 2);
            else       KV_LOAD(FK0, FV0, j + 2);
        }
    }
#undef KV_LOAD

    const float linv0 = 1.0f / li0;
    const float linv1 = 1.0f / li1;
    const size_t r0g = (size_t)(b * S_ + q0 + row0) * (H_ * VD_) + h * VD_;
    const size_t r1g = (size_t)(b * S_ + q0 + row1) * (H_ * VD_) + h * VD_;
#pragma unroll
    for (int nt = 0; nt < 8; nt++) {
        const int col = wc * 64 + nt * 8 + tig * 2;
        *(float2*)&Out[r0g + col] =
            make_float2(to_tf32(acc[nt][0] * linv0), to_tf32(acc[nt][1] * linv0));
        *(float2*)&Out[r1g + col] =
            make_float2(to_tf32(acc[nt][2] * linv1), to_tf32(acc[nt][3] * linv1));
    }
}

// ---------------------------------------------------------------------------
// Launch: head fork (q-proj || ckv chain) + tail pipeline (flash halves
// overlapped with the matching row-halves of the wo projection).
// ---------------------------------------------------------------------------
extern "C" void kernel_launch(void* const* d_in, const int* in_sizes, int n_in,
                              void* d_out, int out_size) {
    const float* x      = (const float*)d_in[0];
    const float* rope   = (const float*)d_in[1];
    const float* wq     = (const float*)d_in[2];
    const float* wkva   = (const float*)d_in[3];
    const float* norm_w = (const float*)d_in[4];
    const float* wkvb   = (const float*)d_in[5];
    const float* wo     = (const float*)d_in[6];
    float* out = (float*)d_out;

    float *p_qckv, *p_norm, *p_kv, *p_qf, *p_kf, *p_v, *p_attn;
    float *p_xr, *p_wqkva, *p_wkvbr, *p_wor;
    cudaGetSymbolAddress((void**)&p_qckv,  g_qckv);
    cudaGetSymbolAddress((void**)&p_norm,  g_norm);
    cudaGetSymbolAddress((void**)&p_kv,    g_kv);
    cudaGetSymbolAddress((void**)&p_qf,    g_qf);
    cudaGetSymbolAddress((void**)&p_kf,    g_kf);
    cudaGetSymbolAddress((void**)&p_v,     g_v);
    cudaGetSymbolAddress((void**)&p_attn,  g_attn);
    cudaGetSymbolAddress((void**)&p_xr,    g_xr);
    cudaGetSymbolAddress((void**)&p_wqkva, g_wqkva);
    cudaGetSymbolAddress((void**)&p_wkvbr, g_wkvbr);
    cudaGetSymbolAddress((void**)&p_wor,   g_wor);

    cudaFuncSetAttribute(mma_gemm, cudaFuncAttributeMaxDynamicSharedMemorySize,
                         MG_SMEM_BYTES);
    cudaFuncSetAttribute(flash_mma, cudaFuncAttributeMaxDynamicSharedMemorySize,
                         FL_SMEM_BYTES);

    static cudaStream_t s1 = nullptr;
    static cudaEvent_t  e0 = nullptr, e1 = nullptr, e2 = nullptr, e4 = nullptr;
    if (s1 == nullptr) {
        cudaStreamCreateWithFlags(&s1, cudaStreamNonBlocking);
        cudaEventCreateWithFlags(&e0, cudaEventDisableTiming);
        cudaEventCreateWithFlags(&e1, cudaEventDisableTiming);
        cudaEventCreateWithFlags(&e2, cudaEventDisableTiming);
        cudaEventCreateWithFlags(&e4, cudaEventDisableTiming);
    }

    // s1: round wq immediately (independent of x)
    round_tf32_kernel<<<1024, 256, 0, s1>>>((const float4*)wq, (float4*)p_wqkva,
                                            H_ * QD_ * DIM_ / 4);
    // main: round x
    round_tf32_kernel<<<1024, 256>>>((const float4*)x, (float4*)p_xr,
                                     BS_ * DIM_ / 4);
    cudaEventRecord(e0, 0);
    cudaStreamWaitEvent(s1, e0, 0);

    // s1: q-projection tiles (cols 0..3071)
    mma_gemm<<<dim3(12, 32), 256, MG_SMEM_BYTES, s1>>>(p_xr, p_wqkva, p_qckv,
                                                       NQC_, DIM_, 0, 0, 0);
    cudaEventRecord(e1, s1);

    // main: remaining weights, ckv tiles, rmsnorm, kv GEMM
    round3_kernel<<<1024, 256>>>(
        (const float4*)wkva, (float4*)(p_wqkva + (size_t)H_ * QD_ * DIM_),
        (KV_LORA_ + ROPE_) * DIM_ / 4,
        (const float4*)wkvb, (float4*)p_wkvbr, H_ * 256 * KV_LORA_ / 4,
        (const float4*)wo,   (float4*)p_wor,   DIM_ * H_ * VD_ / 4);
    mma_gemm<<<dim3(3, 32), 256, MG_SMEM_BYTES>>>(p_xr, p_wqkva, p_qckv,
                                                  NQC_, DIM_, 12, 0, 0);
    rmsnorm_kernel<<<BS_, 128>>>(p_qckv, norm_w, p_norm);
    mma_gemm<<<dim3(16, 32), 256, MG_SMEM_BYTES>>>(p_norm, p_wkvbr, p_kv,
                                                   H_ * 256, KV_LORA_, 0, 0, 0);

    // join q-projection, then assemble
    cudaStreamWaitEvent(0, e1, 0);
    assemble_kernel<<<BS_, 256>>>(p_qckv, p_kv, rope, p_qf, p_kf, p_v);
    cudaEventRecord(e2, 0);

    // main: heavy flash half (qt 31..16 -> attn rows s in [1024,2047])
    flash_mma<<<dim3(B_ * H_, 16), 256, FL_SMEM_BYTES>>>(p_qf, p_kf, p_v,
                                                         p_attn, 16);
    // s1: light flash half (qt 15..0) concurrent with wo-A below
    cudaStreamWaitEvent(s1, e2, 0);
    flash_mma<<<dim3(B_ * H_, 16), 256, FL_SMEM_BYTES, s1>>>(p_qf, p_kf, p_v,
                                                             p_attn, 0);
    cudaEventRecord(e4, s1);

    // main: wo projection for rows of the heavy half
    //   row tiles {8..15, 24..31}: m_tile = 8 + by + (by>>3)*8
    mma_gemm<<<dim3(8, 16), 256, MG_SMEM_BYTES>>>(p_attn, p_wor, out,
                                                  DIM_, DIM_, 0, 8, 8);
    // join light half, then wo for rows {0..7, 16..23}
    cudaStreamWaitEvent(0, e4, 0);
    mma_gemm<<<dim3(8, 16), 256, MG_SMEM_BYTES>>>(p_attn, p_wor, out,
                                                  DIM_, DIM_, 0, 0, 8);
}